// round 8
// baseline (speedup 1.0000x reference)
#include <cuda_runtime.h>
#include <cstdint>

#define ALPHAF 0.3f
#define EPSF   1e-8f
#define PATW   0.1f

// ---- dynamic smem layout (bytes) ----
#define O_X    0        // X staging: 128 rows x 72 halfs (144B stride) = 18432
#define O_B1   18432    // B1 image: 64 rows x 72 halfs  (wh|wl) = 9216
#define O_B2   27648    // B2 image: 32 rows x 136 halfs (wh|wl) = 8704
#define O_G    36352    // grid tile fp32: 128 x 33 = 16896
#define O_P    53248    // pot: 128 f32
#define O_B1S  53760    // b1: 64 f32
#define O_W1P  54016    // W1[32][:]: 64 f32
#define O_B2S  54272    // b2: 32 f32
#define SMEMSZ 54400

#define XSTR  72   // halfs
#define B1STR 72
#define B2STR 136

static __device__ __forceinline__ void ldm4(uint32_t* r, uint32_t addr) {
    asm volatile("ldmatrix.sync.aligned.m8n8.x4.shared.b16 {%0,%1,%2,%3}, [%4];"
                 : "=r"(r[0]), "=r"(r[1]), "=r"(r[2]), "=r"(r[3]) : "r"(addr));
}
static __device__ __forceinline__ void mma16816(float* c, const uint32_t* a, const uint32_t* b) {
    asm volatile(
        "mma.sync.aligned.m16n8k16.row.col.f32.bf16.bf16.f32 "
        "{%0,%1,%2,%3},{%4,%5,%6,%7},{%8,%9},{%0,%1,%2,%3};"
        : "+f"(c[0]), "+f"(c[1]), "+f"(c[2]), "+f"(c[3])
        : "r"(a[0]), "r"(a[1]), "r"(a[2]), "r"(a[3]), "r"(b[0]), "r"(b[1]));
}
static __device__ __forceinline__ unsigned short bfbits(float v) {
    unsigned short r;
    asm("cvt.rn.bf16.f32 %0, %1;" : "=h"(r) : "f"(v));
    return r;
}
static __device__ __forceinline__ float bf2f(unsigned short b) {
    return __uint_as_float((uint32_t)b << 16);
}
static __device__ __forceinline__ uint32_t packbf2(float lo, float hi) {
    uint32_t r;
    asm("cvt.rn.bf16x2.f32 %0, %1, %2;" : "=r"(r) : "f"(hi), "f"(lo));
    return r;
}
static __device__ __forceinline__ uint32_t split2(float v0, float v1, uint32_t& plo) {
    unsigned short h0 = bfbits(v0), h1 = bfbits(v1);
    unsigned short l0 = bfbits(v0 - bf2f(h0));
    unsigned short l1 = bfbits(v1 - bf2f(h1));
    plo = (uint32_t)l0 | ((uint32_t)l1 << 16);
    return (uint32_t)h0 | ((uint32_t)h1 << 16);
}

__global__ void __launch_bounds__(128, 4)
be_mma(const float* __restrict__ grid, const float* __restrict__ pot,
       const float* __restrict__ W1,   const float* __restrict__ b1,
       const float* __restrict__ W2,   const float* __restrict__ b2,
       float* __restrict__ out)
{
    extern __shared__ __align__(16) unsigned char sm[];
    float* gsm = (float*)(sm + O_G);
    float* psm = (float*)(sm + O_P);
    float* b1s = (float*)(sm + O_B1S);
    float* w1p = (float*)(sm + O_W1P);
    float* b2s = (float*)(sm + O_B2S);
    unsigned short* img1 = (unsigned short*)(sm + O_B1);
    unsigned short* img2 = (unsigned short*)(sm + O_B2);

    const int tid  = threadIdx.x;
    const int lane = tid & 31;
    const int w    = tid >> 5;

    const uint32_t xs_b = (uint32_t)__cvta_generic_to_shared(sm + O_X);
    const uint32_t b1_b = (uint32_t)__cvta_generic_to_shared(sm + O_B1);
    const uint32_t b2_b = (uint32_t)__cvta_generic_to_shared(sm + O_B2);

    // ---- phase 1a: grid tile -> gsm (coalesced) ----
    {
        const uint4* gsrc = (const uint4*)(grid + (size_t)blockIdx.x * 4096);
        #pragma unroll
        for (int j = 0; j < 8; j++) {
            int e4 = tid + 128 * j;
            uint4 v = gsrc[e4];
            int row = e4 >> 3, c = (e4 & 7) * 4;
            float* d = gsm + row * 33 + c;
            d[0] = __uint_as_float(v.x); d[1] = __uint_as_float(v.y);
            d[2] = __uint_as_float(v.z); d[3] = __uint_as_float(v.w);
        }
    }
    psm[tid] = pot[(size_t)blockIdx.x * 128 + tid];

    // ---- phase 1b: weight split directly from global (coalesced LDG) ----
    if (tid < 64) {                          // W1 column n = tid
        const int n = tid;
        uint32_t ph[16], pl[16];
        #pragma unroll
        for (int kk = 0; kk < 16; kk++)
            ph[kk] = split2(W1[(2*kk)*64 + n], W1[(2*kk+1)*64 + n], pl[kk]);
        uint4* dh = (uint4*)(img1 + n * B1STR);
        uint4* dl = (uint4*)(img1 + n * B1STR + 32);
        #pragma unroll
        for (int q = 0; q < 4; q++) {
            dh[q] = make_uint4(ph[4*q], ph[4*q+1], ph[4*q+2], ph[4*q+3]);
            dl[q] = make_uint4(pl[4*q], pl[4*q+1], pl[4*q+2], pl[4*q+3]);
        }
        w1p[n] = W1[32 * 64 + n];
        if (n < 64) b1s[n] = b1[n];
        if (n < 32) b2s[n] = b2[n];
    } else {                                 // W2 column n2, K-half kh
        const int n2 = (tid - 64) >> 1;
        const int kh = (tid & 1) * 32;
        uint32_t ph[16], pl[16];
        #pragma unroll
        for (int kk = 0; kk < 16; kk++) {
            int k = kh + 2 * kk;
            ph[kk] = split2(W2[k*32 + n2], W2[(k+1)*32 + n2], pl[kk]);
        }
        uint4* dh = (uint4*)(img2 + n2 * B2STR + kh);
        uint4* dl = (uint4*)(img2 + n2 * B2STR + 64 + kh);
        #pragma unroll
        for (int q = 0; q < 4; q++) {
            dh[q] = make_uint4(ph[4*q], ph[4*q+1], ph[4*q+2], ph[4*q+3]);
            dl[q] = make_uint4(pl[4*q], pl[4*q+1], pl[4*q+2], pl[4*q+3]);
        }
    }
    __syncthreads();     // the ONLY block-wide barrier

    // ---- phase 2: per-pixel x = g + 0.1*g^3/(||g^3||+eps)*||g||, split ----
    {
        float gv[32];
        #pragma unroll
        for (int c = 0; c < 32; c++) gv[c] = gsm[tid * 33 + c];
        float gn2 = 0.f, cn2 = 0.f;
        #pragma unroll
        for (int i = 0; i < 32; i++) {
            float q = gv[i] * gv[i];
            gn2 += q;
            float c3 = q * gv[i];
            cn2 = fmaf(c3, c3, cn2);
        }
        const float t = PATW * sqrtf(gn2) / (sqrtf(cn2) + EPSF);
        uint32_t xh[16], xl[16];
        #pragma unroll
        for (int i = 0; i < 16; i++) {
            float x0 = fmaf(t * gv[2*i]   * gv[2*i],   gv[2*i],   gv[2*i]);
            float x1 = fmaf(t * gv[2*i+1] * gv[2*i+1], gv[2*i+1], gv[2*i+1]);
            uint32_t p = packbf2(x0, x1);
            xh[i] = p;
            float l0 = x0 - __uint_as_float(p << 16);
            float l1 = x1 - __uint_as_float(p & 0xFFFF0000u);
            xl[i] = packbf2(l0, l1);
        }
        uint4* xr = (uint4*)(sm + O_X + tid * (XSTR * 2));
        #pragma unroll
        for (int j = 0; j < 4; j++)
            xr[j] = make_uint4(xh[4*j], xh[4*j+1], xh[4*j+2], xh[4*j+3]);
        #pragma unroll
        for (int j = 0; j < 4; j++)
            xr[4 + j] = make_uint4(xl[4*j], xl[4*j+1], xl[4*j+2], xl[4*j+3]);
    }
    __syncwarp();

    const int m0 = w * 32;

    // ---- A fragments (xh cols 0..31, xl cols 32..63) ----
    uint32_t Ah[2][2][4], Al[2][2][4];
    #pragma unroll
    for (int mt = 0; mt < 2; mt++)
        #pragma unroll
        for (int ks = 0; ks < 2; ks++) {
            uint32_t base = xs_b + (uint32_t)(m0 + mt*16 + (lane & 15)) * (XSTR*2)
                          + ((lane >> 4) << 4);
            ldm4(Ah[mt][ks], base + (uint32_t)(ks*16) * 2);
            ldm4(Al[mt][ks], base + (uint32_t)(32 + ks*16) * 2);
        }

    // ---- B1 wh fragments ----
    uint32_t Bf[2][8][2];
    #pragma unroll
    for (int ks = 0; ks < 2; ks++)
        #pragma unroll
        for (int np = 0; np < 4; np++) {
            uint32_t a = b1_b + (uint32_t)(np*16 + ((lane>>4)<<3) + (lane&7)) * (B1STR*2)
                       + (uint32_t)(ks*16)*2 + (((lane>>3)&1) << 4);
            ldm4(&Bf[ks][2*np][0], a);
        }

    // ---- C1 init: b1[n] + pot[m]*W1[32][n] (fp32 exact) ----
    float C[2][8][4];
    const int nb = (lane & 3) * 2;
    float pv[2][2];
    #pragma unroll
    for (int mt = 0; mt < 2; mt++) {
        pv[mt][0] = psm[m0 + mt*16 + (lane >> 2)];
        pv[mt][1] = psm[m0 + mt*16 + (lane >> 2) + 8];
    }
    #pragma unroll
    for (int nt = 0; nt < 8; nt++) {
        int n = nt*8 + nb;
        float bb0 = b1s[n], bb1 = b1s[n+1], w0 = w1p[n], w1v = w1p[n+1];
        #pragma unroll
        for (int mt = 0; mt < 2; mt++) {
            C[mt][nt][0] = fmaf(pv[mt][0], w0,  bb0);
            C[mt][nt][1] = fmaf(pv[mt][0], w1v, bb1);
            C[mt][nt][2] = fmaf(pv[mt][1], w0,  bb0);
            C[mt][nt][3] = fmaf(pv[mt][1], w1v, bb1);
        }
    }

    // ---- GEMM1: xh*wh + xl*wh, then xh*wl ----
    #pragma unroll
    for (int ks = 0; ks < 2; ks++)
        #pragma unroll
        for (int mt = 0; mt < 2; mt++)
            #pragma unroll
            for (int nt = 0; nt < 8; nt++)
                mma16816(C[mt][nt], Ah[mt][ks], Bf[ks][nt]);
    #pragma unroll
    for (int ks = 0; ks < 2; ks++)
        #pragma unroll
        for (int mt = 0; mt < 2; mt++)
            #pragma unroll
            for (int nt = 0; nt < 8; nt++)
                mma16816(C[mt][nt], Al[mt][ks], Bf[ks][nt]);
    #pragma unroll
    for (int ks = 0; ks < 2; ks++)                 // reload B with wl (cols 32..63)
        #pragma unroll
        for (int np = 0; np < 4; np++) {
            uint32_t a = b1_b + (uint32_t)(np*16 + ((lane>>4)<<3) + (lane&7)) * (B1STR*2)
                       + (uint32_t)(32 + ks*16)*2 + (((lane>>3)&1) << 4);
            ldm4(&Bf[ks][2*np][0], a);
        }
    #pragma unroll
    for (int ks = 0; ks < 2; ks++)
        #pragma unroll
        for (int mt = 0; mt < 2; mt++)
            #pragma unroll
            for (int nt = 0; nt < 8; nt++)
                mma16816(C[mt][nt], Ah[mt][ks], Bf[ks][nt]);

    // ---- relu + split -> A2 fragments straight from C regs ----
    uint32_t Hh[2][4][4], Hl[2][4][4];
    #pragma unroll
    for (int mt = 0; mt < 2; mt++)
        #pragma unroll
        for (int ks = 0; ks < 4; ks++)
            #pragma unroll
            for (int q = 0; q < 4; q++) {
                int nt = 2*ks + (q >> 1);
                float hA = fmaxf(C[mt][nt][(q & 1) * 2],     0.f);
                float hB = fmaxf(C[mt][nt][(q & 1) * 2 + 1], 0.f);
                uint32_t p = packbf2(hA, hB);
                Hh[mt][ks][q] = p;
                float lA = hA - __uint_as_float(p << 16);
                float lB = hB - __uint_as_float(p & 0xFFFF0000u);
                Hl[mt][ks][q] = packbf2(lA, lB);
            }

    // ---- GEMM2: hh*w2h + hl*w2h, then hh*w2l ----
    float C2[2][4][4];
    #pragma unroll
    for (int mt = 0; mt < 2; mt++)
        #pragma unroll
        for (int nt = 0; nt < 4; nt++)
            #pragma unroll
            for (int q = 0; q < 4; q++) C2[mt][nt][q] = 0.f;

    uint32_t B2f[4][2];
    #pragma unroll
    for (int ks = 0; ks < 4; ks++) {
        #pragma unroll
        for (int np = 0; np < 2; np++) {
            uint32_t a = b2_b + (uint32_t)(np*16 + ((lane>>4)<<3) + (lane&7)) * (B2STR*2)
                       + (uint32_t)(ks*16)*2 + (((lane>>3)&1) << 4);
            ldm4(&B2f[2*np][0], a);
        }
        #pragma unroll
        for (int mt = 0; mt < 2; mt++)
            #pragma unroll
            for (int nt = 0; nt < 4; nt++) {
                mma16816(C2[mt][nt], Hh[mt][ks], B2f[nt]);
                mma16816(C2[mt][nt], Hl[mt][ks], B2f[nt]);
            }
    }
    #pragma unroll
    for (int ks = 0; ks < 4; ks++) {
        #pragma unroll
        for (int np = 0; np < 2; np++) {
            uint32_t a = b2_b + (uint32_t)(np*16 + ((lane>>4)<<3) + (lane&7)) * (B2STR*2)
                       + (uint32_t)(64 + ks*16)*2 + (((lane>>3)&1) << 4);
            ldm4(&B2f[2*np][0], a);
        }
        #pragma unroll
        for (int mt = 0; mt < 2; mt++)
            #pragma unroll
            for (int nt = 0; nt < 4; nt++)
                mma16816(C2[mt][nt], Hh[mt][ks], B2f[nt]);
    }

    // ---- epilogue: direct fragment-layout STG.64 (no smem round-trip) ----
    {
        float* outb = out + (size_t)blockIdx.x * 4096;
        #pragma unroll
        for (int mt = 0; mt < 2; mt++) {
            int r0 = m0 + mt*16 + (lane >> 2);
            int r1 = r0 + 8;
            #pragma unroll
            for (int nt = 0; nt < 4; nt++) {
                int n = nt*8 + nb;
                float bb0 = b2s[n], bb1 = b2s[n+1];
                float2 o0, o1;
                o0.x = fmaf(ALPHAF, gsm[r0*33 + n],     C2[mt][nt][0] + bb0);
                o0.y = fmaf(ALPHAF, gsm[r0*33 + n + 1], C2[mt][nt][1] + bb1);
                o1.x = fmaf(ALPHAF, gsm[r1*33 + n],     C2[mt][nt][2] + bb0);
                o1.y = fmaf(ALPHAF, gsm[r1*33 + n + 1], C2[mt][nt][3] + bb1);
                *(float2*)(outb + r0*32 + n) = o0;
                *(float2*)(outb + r1*32 + n) = o1;
            }
        }
    }
}

extern "C" void kernel_launch(void* const* d_in, const int* in_sizes, int n_in,
                              void* d_out, int out_size) {
    const float* grid = (const float*)d_in[0];
    const float* pot  = (const float*)d_in[1];
    const float* W1   = (const float*)d_in[2];
    const float* b1   = (const float*)d_in[3];
    const float* W2   = (const float*)d_in[4];
    const float* b2   = (const float*)d_in[5];
    float* out = (float*)d_out;

    cudaFuncSetAttribute(be_mma, cudaFuncAttributeMaxDynamicSharedMemorySize, SMEMSZ);
    be_mma<<<8192, 128, SMEMSZ>>>(grid, pot, W1, b1, W2, b2, out);
}

// round 9
// speedup vs baseline: 1.4598x; 1.4598x over previous
#include <cuda_runtime.h>
#include <cstdint>

#define ALPHAF 0.3f
#define EPSF   1e-8f
#define PATW   0.1f

#define GRIDC  608          // 152 SMs x 4 CTAs, persistent
#define NTILES 8192

// ---- dynamic smem layout (bytes) ----
#define RSTR   144          // region row stride (bytes): g fp32(128B)+pad, X 72 halfs
#define O_R0   0            // region 0: 128 rows x 144B = 18432   (init: raw W1 stage)
#define O_R1   18432        // region 1: 18432                      (init: raw W2 stage)
#define O_B1   36864        // B1 image: 64 x 72 halfs = 9216
#define O_B2   46080        // B2 image: 32 x 136 halfs = 8704
#define O_P0   54784        // pot buf 0: 128 f32
#define O_P1   55296        // pot buf 1
#define O_B1S  55808        // b1: 64 f32
#define O_W1P  56064        // W1[32][:]: 64 f32
#define O_B2S  56320        // b2: 32 f32
#define SMEMSZ 56448

#define B1STR 72
#define B2STR 136

static __device__ __forceinline__ void ldm4(uint32_t* r, uint32_t addr) {
    asm volatile("ldmatrix.sync.aligned.m8n8.x4.shared.b16 {%0,%1,%2,%3}, [%4];"
                 : "=r"(r[0]), "=r"(r[1]), "=r"(r[2]), "=r"(r[3]) : "r"(addr));
}
static __device__ __forceinline__ void mma16816(float* c, const uint32_t* a, const uint32_t* b) {
    asm volatile(
        "mma.sync.aligned.m16n8k16.row.col.f32.bf16.bf16.f32 "
        "{%0,%1,%2,%3},{%4,%5,%6,%7},{%8,%9},{%0,%1,%2,%3};"
        : "+f"(c[0]), "+f"(c[1]), "+f"(c[2]), "+f"(c[3])
        : "r"(a[0]), "r"(a[1]), "r"(a[2]), "r"(a[3]), "r"(b[0]), "r"(b[1]));
}
static __device__ __forceinline__ unsigned short bfbits(float v) {
    unsigned short r;
    asm("cvt.rn.bf16.f32 %0, %1;" : "=h"(r) : "f"(v));
    return r;
}
static __device__ __forceinline__ float bf2f(unsigned short b) {
    return __uint_as_float((uint32_t)b << 16);
}
static __device__ __forceinline__ uint32_t packbf2(float lo, float hi) {
    uint32_t r;
    asm("cvt.rn.bf16x2.f32 %0, %1, %2;" : "=r"(r) : "f"(hi), "f"(lo));
    return r;
}
static __device__ __forceinline__ uint32_t split2(float v0, float v1, uint32_t& plo) {
    unsigned short h0 = bfbits(v0), h1 = bfbits(v1);
    unsigned short l0 = bfbits(v0 - bf2f(h0));
    unsigned short l1 = bfbits(v1 - bf2f(h1));
    plo = (uint32_t)l0 | ((uint32_t)l1 << 16);
    return (uint32_t)h0 | ((uint32_t)h1 << 16);
}
static __device__ __forceinline__ void cpa16(uint32_t dst, const void* src) {
    asm volatile("cp.async.ca.shared.global [%0], [%1], 16;" :: "r"(dst), "l"(src));
}
static __device__ __forceinline__ void cpa4(uint32_t dst, const void* src) {
    asm volatile("cp.async.ca.shared.global [%0], [%1], 4;" :: "r"(dst), "l"(src));
}

__global__ void __launch_bounds__(128, 4)
be_mma(const float* __restrict__ grid, const float* __restrict__ pot,
       const float* __restrict__ W1,   const float* __restrict__ b1,
       const float* __restrict__ W2,   const float* __restrict__ b2,
       float* __restrict__ out)
{
    extern __shared__ __align__(16) unsigned char sm[];
    float* b1s = (float*)(sm + O_B1S);
    float* w1p = (float*)(sm + O_W1P);
    float* b2s = (float*)(sm + O_B2S);
    unsigned short* img1 = (unsigned short*)(sm + O_B1);
    unsigned short* img2 = (unsigned short*)(sm + O_B2);

    const int tid  = threadIdx.x;
    const int lane = tid & 31;
    const int w    = tid >> 5;
    const int m0   = w * 32;

    const uint32_t r0b  = (uint32_t)__cvta_generic_to_shared(sm + O_R0);
    const uint32_t r1b  = (uint32_t)__cvta_generic_to_shared(sm + O_R1);
    const uint32_t b1_b = (uint32_t)__cvta_generic_to_shared(sm + O_B1);
    const uint32_t b2_b = (uint32_t)__cvta_generic_to_shared(sm + O_B2);
    const uint32_t p0b  = (uint32_t)__cvta_generic_to_shared(sm + O_P0);
    const uint32_t p1b  = (uint32_t)__cvta_generic_to_shared(sm + O_P1);

    // ================= one-time weight build (regions used as raw staging) ==
    {
        float* rw1 = (float*)(sm + O_R0);   // 2112 f32
        float* rw2 = (float*)(sm + O_R1);   // 2048 f32
        #pragma unroll
        for (int i = tid; i < 2112; i += 128) rw1[i] = W1[i];
        #pragma unroll
        for (int i = tid; i < 2048; i += 128) rw2[i] = W2[i];
        if (tid < 64) b1s[tid] = b1[tid];
        if (tid < 32) b2s[tid] = b2[tid];
        __syncthreads();

        if (tid < 64) {                     // W1 column n = tid
            const int n = tid;
            uint32_t ph[16], pl[16];
            #pragma unroll
            for (int kk = 0; kk < 16; kk++)
                ph[kk] = split2(rw1[(2*kk)*64 + n], rw1[(2*kk+1)*64 + n], pl[kk]);
            uint4* dh = (uint4*)(img1 + n * B1STR);
            uint4* dl = (uint4*)(img1 + n * B1STR + 32);
            #pragma unroll
            for (int q = 0; q < 4; q++) {
                dh[q] = make_uint4(ph[4*q], ph[4*q+1], ph[4*q+2], ph[4*q+3]);
                dl[q] = make_uint4(pl[4*q], pl[4*q+1], pl[4*q+2], pl[4*q+3]);
            }
            w1p[n] = rw1[32 * 64 + n];
        } else {                            // W2 column n2, K-half kh
            const int n2 = (tid - 64) >> 1;
            const int kh = (tid & 1) * 32;
            uint32_t ph[16], pl[16];
            #pragma unroll
            for (int kk = 0; kk < 16; kk++) {
                int k = kh + 2 * kk;
                ph[kk] = split2(rw2[k*32 + n2], rw2[(k+1)*32 + n2], pl[kk]);
            }
            uint4* dh = (uint4*)(img2 + n2 * B2STR + kh);
            uint4* dl = (uint4*)(img2 + n2 * B2STR + 64 + kh);
            #pragma unroll
            for (int q = 0; q < 4; q++) {
                dh[q] = make_uint4(ph[4*q], ph[4*q+1], ph[4*q+2], ph[4*q+3]);
                dl[q] = make_uint4(pl[4*q], pl[4*q+1], pl[4*q+2], pl[4*q+3]);
            }
        }
        __syncthreads();
    }

    // ================= persistent per-warp tile loop ========================
    const uint32_t rB[2] = { r0b, r1b };
    const uint32_t pB[2] = { p0b, p1b };
    const unsigned char* const rP[2] = { sm + O_R0, sm + O_R1 };
    const unsigned char* const pP[2] = { sm + O_P0, sm + O_P1 };

    // prologue: prefetch first tile's warp-quarter into region 0 / pot buf 0
    {
        const float* src = grid + (size_t)blockIdx.x * 4096 + m0 * 32;
        #pragma unroll
        for (int c = 0; c < 8; c++) {
            int flat = lane + 32 * c;                    // 16B chunks
            int row = flat >> 3, q = flat & 7;
            cpa16(rB[0] + (uint32_t)(m0 + row) * RSTR + q * 16, src + flat * 4);
        }
        cpa4(pB[0] + (uint32_t)(m0 + lane) * 4, pot + (size_t)blockIdx.x * 128 + m0 + lane);
        asm volatile("cp.async.commit_group;");
    }

    int cur = 0;
    for (int t = blockIdx.x; t < NTILES; t += GRIDC) {
        asm volatile("cp.async.wait_group 0;");          // per-warp: own prefetch done

        const unsigned char* gR = rP[cur];               // g(t), rows m0.. (warp-private)
        const uint32_t      xRb = rB[cur ^ 1];           // X region
        const unsigned char* xR = rP[cur ^ 1];
        const float*        psm = (const float*)pP[cur];

        // ---- X build: x = g + 0.1*g^3/(||g^3||+eps)*||g||, bf16 hi/lo ----
        {
            float gv[32];
            const uint4* grow = (const uint4*)(gR + tid * RSTR);
            #pragma unroll
            for (int q = 0; q < 8; q++) {
                uint4 v = grow[q];
                gv[4*q+0] = __uint_as_float(v.x); gv[4*q+1] = __uint_as_float(v.y);
                gv[4*q+2] = __uint_as_float(v.z); gv[4*q+3] = __uint_as_float(v.w);
            }
            float gn2 = 0.f, cn2 = 0.f;
            #pragma unroll
            for (int i = 0; i < 32; i++) {
                float q = gv[i] * gv[i];
                gn2 += q;
                float c3 = q * gv[i];
                cn2 = fmaf(c3, c3, cn2);
            }
            const float tt = PATW * sqrtf(gn2) / (sqrtf(cn2) + EPSF);
            uint32_t xh[16], xl[16];
            #pragma unroll
            for (int i = 0; i < 16; i++) {
                float x0 = fmaf(tt * gv[2*i]   * gv[2*i],   gv[2*i],   gv[2*i]);
                float x1 = fmaf(tt * gv[2*i+1] * gv[2*i+1], gv[2*i+1], gv[2*i+1]);
                uint32_t p = packbf2(x0, x1);
                xh[i] = p;
                float l0 = x0 - __uint_as_float(p << 16);
                float l1 = x1 - __uint_as_float(p & 0xFFFF0000u);
                xl[i] = packbf2(l0, l1);
            }
            uint4* xr = (uint4*)(xR + tid * RSTR);
            #pragma unroll
            for (int j = 0; j < 4; j++)
                xr[j] = make_uint4(xh[4*j], xh[4*j+1], xh[4*j+2], xh[4*j+3]);
            #pragma unroll
            for (int j = 0; j < 4; j++)
                xr[4 + j] = make_uint4(xl[4*j], xl[4*j+1], xl[4*j+2], xl[4*j+3]);
        }
        __syncwarp();

        // ---- A fragments ----
        uint32_t Ah[2][2][4], Al[2][2][4];
        #pragma unroll
        for (int mt = 0; mt < 2; mt++)
            #pragma unroll
            for (int ks = 0; ks < 2; ks++) {
                uint32_t base = xRb + (uint32_t)(m0 + mt*16 + (lane & 15)) * RSTR
                              + ((lane >> 4) << 4);
                ldm4(Ah[mt][ks], base + (uint32_t)(ks*16) * 2);
                ldm4(Al[mt][ks], base + (uint32_t)(32 + ks*16) * 2);
            }
        __syncwarp();   // all lanes' X reads done before prefetch clobbers region

        // ---- prefetch tile t+GRIDC into X region (dead now) ----
        {
            int tn = t + GRIDC;
            if (tn < NTILES) {
                const float* src = grid + (size_t)tn * 4096 + m0 * 32;
                #pragma unroll
                for (int c = 0; c < 8; c++) {
                    int flat = lane + 32 * c;
                    int row = flat >> 3, q = flat & 7;
                    cpa16(xRb + (uint32_t)(m0 + row) * RSTR + q * 16, src + flat * 4);
                }
                cpa4(pB[cur ^ 1] + (uint32_t)(m0 + lane) * 4,
                     pot + (size_t)tn * 128 + m0 + lane);
            }
            asm volatile("cp.async.commit_group;");
        }

        // ---- B1 wh fragments ----
        uint32_t Bf[2][8][2];
        #pragma unroll
        for (int ks = 0; ks < 2; ks++)
            #pragma unroll
            for (int np = 0; np < 4; np++) {
                uint32_t a = b1_b + (uint32_t)(np*16 + ((lane>>4)<<3) + (lane&7)) * (B1STR*2)
                           + (uint32_t)(ks*16)*2 + (((lane>>3)&1) << 4);
                ldm4(&Bf[ks][2*np][0], a);
            }

        // ---- C1 init: b1[n] + pot[m]*W1[32][n] ----
        float C[2][8][4];
        const int nb = (lane & 3) * 2;
        float pv[2][2];
        #pragma unroll
        for (int mt = 0; mt < 2; mt++) {
            pv[mt][0] = psm[m0 + mt*16 + (lane >> 2)];
            pv[mt][1] = psm[m0 + mt*16 + (lane >> 2) + 8];
        }
        #pragma unroll
        for (int nt = 0; nt < 8; nt++) {
            int n = nt*8 + nb;
            float bb0 = b1s[n], bb1 = b1s[n+1], w0 = w1p[n], w1v = w1p[n+1];
            #pragma unroll
            for (int mt = 0; mt < 2; mt++) {
                C[mt][nt][0] = fmaf(pv[mt][0], w0,  bb0);
                C[mt][nt][1] = fmaf(pv[mt][0], w1v, bb1);
                C[mt][nt][2] = fmaf(pv[mt][1], w0,  bb0);
                C[mt][nt][3] = fmaf(pv[mt][1], w1v, bb1);
            }
        }

        // ---- GEMM1: xh*wh + xl*wh, then xh*wl ----
        #pragma unroll
        for (int ks = 0; ks < 2; ks++)
            #pragma unroll
            for (int mt = 0; mt < 2; mt++)
                #pragma unroll
                for (int nt = 0; nt < 8; nt++)
                    mma16816(C[mt][nt], Ah[mt][ks], Bf[ks][nt]);
        #pragma unroll
        for (int ks = 0; ks < 2; ks++)
            #pragma unroll
            for (int mt = 0; mt < 2; mt++)
                #pragma unroll
                for (int nt = 0; nt < 8; nt++)
                    mma16816(C[mt][nt], Al[mt][ks], Bf[ks][nt]);
        #pragma unroll
        for (int ks = 0; ks < 2; ks++)
            #pragma unroll
            for (int np = 0; np < 4; np++) {
                uint32_t a = b1_b + (uint32_t)(np*16 + ((lane>>4)<<3) + (lane&7)) * (B1STR*2)
                           + (uint32_t)(32 + ks*16)*2 + (((lane>>3)&1) << 4);
                ldm4(&Bf[ks][2*np][0], a);
            }
        #pragma unroll
        for (int ks = 0; ks < 2; ks++)
            #pragma unroll
            for (int mt = 0; mt < 2; mt++)
                #pragma unroll
                for (int nt = 0; nt < 8; nt++)
                    mma16816(C[mt][nt], Ah[mt][ks], Bf[ks][nt]);

        // ---- relu + split -> A2 fragments ----
        uint32_t Hh[2][4][4], Hl[2][4][4];
        #pragma unroll
        for (int mt = 0; mt < 2; mt++)
            #pragma unroll
            for (int ks = 0; ks < 4; ks++)
                #pragma unroll
                for (int q = 0; q < 4; q++) {
                    int nt = 2*ks + (q >> 1);
                    float hA = fmaxf(C[mt][nt][(q & 1) * 2],     0.f);
                    float hB = fmaxf(C[mt][nt][(q & 1) * 2 + 1], 0.f);
                    uint32_t p = packbf2(hA, hB);
                    Hh[mt][ks][q] = p;
                    float lA = hA - __uint_as_float(p << 16);
                    float lB = hB - __uint_as_float(p & 0xFFFF0000u);
                    Hl[mt][ks][q] = packbf2(lA, lB);
                }

        // ---- GEMM2 ----
        float C2[2][4][4];
        #pragma unroll
        for (int mt = 0; mt < 2; mt++)
            #pragma unroll
            for (int nt = 0; nt < 4; nt++)
                #pragma unroll
                for (int q = 0; q < 4; q++) C2[mt][nt][q] = 0.f;

        uint32_t B2f[4][2];
        #pragma unroll
        for (int ks = 0; ks < 4; ks++) {
            #pragma unroll
            for (int np = 0; np < 2; np++) {
                uint32_t a = b2_b + (uint32_t)(np*16 + ((lane>>4)<<3) + (lane&7)) * (B2STR*2)
                           + (uint32_t)(ks*16)*2 + (((lane>>3)&1) << 4);
                ldm4(&B2f[2*np][0], a);
            }
            #pragma unroll
            for (int mt = 0; mt < 2; mt++)
                #pragma unroll
                for (int nt = 0; nt < 4; nt++) {
                    mma16816(C2[mt][nt], Hh[mt][ks], B2f[nt]);
                    mma16816(C2[mt][nt], Hl[mt][ks], B2f[nt]);
                }
        }
        #pragma unroll
        for (int ks = 0; ks < 4; ks++) {
            #pragma unroll
            for (int np = 0; np < 2; np++) {
                uint32_t a = b2_b + (uint32_t)(np*16 + ((lane>>4)<<3) + (lane&7)) * (B2STR*2)
                           + (uint32_t)(64 + ks*16)*2 + (((lane>>3)&1) << 4);
                ldm4(&B2f[2*np][0], a);
            }
            #pragma unroll
            for (int mt = 0; mt < 2; mt++)
                #pragma unroll
                for (int nt = 0; nt < 4; nt++)
                    mma16816(C2[mt][nt], Hh[mt][ks], B2f[nt]);
        }

        // ---- epilogue: out = C2 + b2 + alpha*g  (direct float2 STG, R5-style) ----
        {
            float* outb = out + (size_t)t * 4096;
            #pragma unroll
            for (int mt = 0; mt < 2; mt++) {
                int r0 = m0 + mt*16 + (lane >> 2);
                int r1 = r0 + 8;
                const float* g0 = (const float*)(gR + r0 * RSTR);
                const float* g1 = (const float*)(gR + r1 * RSTR);
                #pragma unroll
                for (int nt = 0; nt < 4; nt++) {
                    int n = nt*8 + nb;
                    float bb0 = b2s[n], bb1 = b2s[n+1];
                    float2 o0, o1;
                    o0.x = fmaf(ALPHAF, g0[n],     C2[mt][nt][0] + bb0);
                    o0.y = fmaf(ALPHAF, g0[n + 1], C2[mt][nt][1] + bb1);
                    o1.x = fmaf(ALPHAF, g1[n],     C2[mt][nt][2] + bb0);
                    o1.y = fmaf(ALPHAF, g1[n + 1], C2[mt][nt][3] + bb1);
                    *(float2*)(outb + r0*32 + n) = o0;
                    *(float2*)(outb + r1*32 + n) = o1;
                }
            }
        }
        cur ^= 1;
    }
}

extern "C" void kernel_launch(void* const* d_in, const int* in_sizes, int n_in,
                              void* d_out, int out_size) {
    const float* grid = (const float*)d_in[0];
    const float* pot  = (const float*)d_in[1];
    const float* W1   = (const float*)d_in[2];
    const float* b1   = (const float*)d_in[3];
    const float* W2   = (const float*)d_in[4];
    const float* b2   = (const float*)d_in[5];
    float* out = (float*)d_out;

    cudaFuncSetAttribute(be_mma, cudaFuncAttributeMaxDynamicSharedMemorySize, SMEMSZ);
    be_mma<<<GRIDC, 128, SMEMSZ>>>(grid, pot, W1, b1, W2, b2, out);
}

// round 10
// speedup vs baseline: 1.4848x; 1.0171x over previous
#include <cuda_runtime.h>
#include <cstdint>

#define ALPHAF 0.3f
#define EPSF   1e-8f
#define PATW   0.1f

#define GRIDC  608          // 152 SMs x 4 CTAs, persistent
#define NTILES 8192

// ---- dynamic smem layout (bytes) ----
#define RSTR   144          // region row stride: g fp32 (128B)+pad / X 72 halfs
#define O_R0   0            // region 0: 128 x 144 = 18432
#define O_R1   18432        // region 1: 18432 (init: raw W1 @ +0, raw W2 @ +8704)
#define O_B1   36864        // B1 image: 64 x 72 halfs = 9216
#define O_B2   46080        // B2 image: 32 x 136 halfs = 8704
#define O_P0   54784        // pot buf 0: 128 f32
#define O_P1   55296        // pot buf 1
#define O_B1S  55808        // b1: 64 f32
#define O_W1P  56064        // W1[32][:]: 64 f32
#define O_B2S  56320        // b2: 32 f32
#define SMEMSZ 56448

#define B1STR 72
#define B2STR 136

static __device__ __forceinline__ void ldm4(uint32_t* r, uint32_t addr) {
    asm volatile("ldmatrix.sync.aligned.m8n8.x4.shared.b16 {%0,%1,%2,%3}, [%4];"
                 : "=r"(r[0]), "=r"(r[1]), "=r"(r[2]), "=r"(r[3]) : "r"(addr));
}
static __device__ __forceinline__ void mma16816(float* c, const uint32_t* a, const uint32_t* b) {
    asm volatile(
        "mma.sync.aligned.m16n8k16.row.col.f32.bf16.bf16.f32 "
        "{%0,%1,%2,%3},{%4,%5,%6,%7},{%8,%9},{%0,%1,%2,%3};"
        : "+f"(c[0]), "+f"(c[1]), "+f"(c[2]), "+f"(c[3])
        : "r"(a[0]), "r"(a[1]), "r"(a[2]), "r"(a[3]), "r"(b[0]), "r"(b[1]));
}
static __device__ __forceinline__ unsigned short bfbits(float v) {
    unsigned short r;
    asm("cvt.rn.bf16.f32 %0, %1;" : "=h"(r) : "f"(v));
    return r;
}
static __device__ __forceinline__ float bf2f(unsigned short b) {
    return __uint_as_float((uint32_t)b << 16);
}
static __device__ __forceinline__ uint32_t packbf2(float lo, float hi) {
    uint32_t r;
    asm("cvt.rn.bf16x2.f32 %0, %1, %2;" : "=r"(r) : "f"(hi), "f"(lo));
    return r;
}
static __device__ __forceinline__ uint32_t split2(float v0, float v1, uint32_t& plo) {
    unsigned short h0 = bfbits(v0), h1 = bfbits(v1);
    unsigned short l0 = bfbits(v0 - bf2f(h0));
    unsigned short l1 = bfbits(v1 - bf2f(h1));
    plo = (uint32_t)l0 | ((uint32_t)l1 << 16);
    return (uint32_t)h0 | ((uint32_t)h1 << 16);
}
static __device__ __forceinline__ void cpa16(uint32_t dst, const void* src) {
    asm volatile("cp.async.ca.shared.global [%0], [%1], 16;" :: "r"(dst), "l"(src));
}

__global__ void __launch_bounds__(128, 4)
be_mma(const float* __restrict__ grid, const float* __restrict__ pot,
       const float* __restrict__ W1,   const float* __restrict__ b1,
       const float* __restrict__ W2,   const float* __restrict__ b2,
       float* __restrict__ out)
{
    extern __shared__ __align__(16) unsigned char sm[];
    float* b1s = (float*)(sm + O_B1S);
    float* w1p = (float*)(sm + O_W1P);
    float* b2s = (float*)(sm + O_B2S);
    unsigned short* img1 = (unsigned short*)(sm + O_B1);
    unsigned short* img2 = (unsigned short*)(sm + O_B2);

    const int tid  = threadIdx.x;
    const int lane = tid & 31;
    const int w    = tid >> 5;
    const int m0   = w * 32;

    const uint32_t r0b  = (uint32_t)__cvta_generic_to_shared(sm + O_R0);
    const uint32_t r1b  = (uint32_t)__cvta_generic_to_shared(sm + O_R1);
    const uint32_t b1_b = (uint32_t)__cvta_generic_to_shared(sm + O_B1);
    const uint32_t b2_b = (uint32_t)__cvta_generic_to_shared(sm + O_B2);
    const uint32_t p0b  = (uint32_t)__cvta_generic_to_shared(sm + O_P0);
    const uint32_t p1b  = (uint32_t)__cvta_generic_to_shared(sm + O_P1);

    // ===== prologue: prefetch tile-0 warp slice FIRST (into region 0) =====
    {
        const float* src = grid + (size_t)blockIdx.x * 4096 + m0 * 32;
        #pragma unroll
        for (int c = 0; c < 8; c++) {
            int flat = lane + 32 * c;                    // 16B chunks
            int row = flat >> 3, q = flat & 7;
            cpa16(r0b + (uint32_t)(m0 + row) * RSTR + q * 16, src + flat * 4);
        }
        if (lane < 8)
            cpa16(p0b + (uint32_t)(m0 + lane * 4) * 4,
                  pot + (size_t)blockIdx.x * 128 + m0 + lane * 4);
        asm volatile("cp.async.commit_group;");
    }

    // ===== one-time weight build (raw staging entirely inside region 1) ====
    {
        float* rw1 = (float*)(sm + O_R1);          // 2112 f32 (8448 B)
        float* rw2 = (float*)(sm + O_R1 + 8704);   // 2048 f32 (8192 B)
        #pragma unroll
        for (int i = tid; i < 2112; i += 128) rw1[i] = W1[i];
        #pragma unroll
        for (int i = tid; i < 2048; i += 128) rw2[i] = W2[i];
        if (tid < 64) b1s[tid] = b1[tid];
        if (tid < 32) b2s[tid] = b2[tid];
        __syncthreads();

        if (tid < 64) {                     // W1 column n = tid
            const int n = tid;
            uint32_t ph[16], pl[16];
            #pragma unroll
            for (int kk = 0; kk < 16; kk++)
                ph[kk] = split2(rw1[(2*kk)*64 + n], rw1[(2*kk+1)*64 + n], pl[kk]);
            uint4* dh = (uint4*)(img1 + n * B1STR);
            uint4* dl = (uint4*)(img1 + n * B1STR + 32);
            #pragma unroll
            for (int q = 0; q < 4; q++) {
                dh[q] = make_uint4(ph[4*q], ph[4*q+1], ph[4*q+2], ph[4*q+3]);
                dl[q] = make_uint4(pl[4*q], pl[4*q+1], pl[4*q+2], pl[4*q+3]);
            }
            w1p[n] = rw1[32 * 64 + n];
        } else {                            // W2 column n2, K-half kh
            const int n2 = (tid - 64) >> 1;
            const int kh = (tid & 1) * 32;
            uint32_t ph[16], pl[16];
            #pragma unroll
            for (int kk = 0; kk < 16; kk++) {
                int k = kh + 2 * kk;
                ph[kk] = split2(rw2[k*32 + n2], rw2[(k+1)*32 + n2], pl[kk]);
            }
            uint4* dh = (uint4*)(img2 + n2 * B2STR + kh);
            uint4* dl = (uint4*)(img2 + n2 * B2STR + 64 + kh);
            #pragma unroll
            for (int q = 0; q < 4; q++) {
                dh[q] = make_uint4(ph[4*q], ph[4*q+1], ph[4*q+2], ph[4*q+3]);
                dl[q] = make_uint4(pl[4*q], pl[4*q+1], pl[4*q+2], pl[4*q+3]);
            }
        }
        __syncthreads();
    }

    // ===== persistent per-warp tile loop ====================================
    const uint32_t rB[2] = { r0b, r1b };
    const uint32_t pB[2] = { p0b, p1b };
    const unsigned char* const rP[2] = { sm + O_R0, sm + O_R1 };
    const unsigned char* const pP[2] = { sm + O_P0, sm + O_P1 };

    int cur = 0;
    for (int t = blockIdx.x; t < NTILES; t += GRIDC) {
        asm volatile("cp.async.wait_group 0;");          // own prefetch landed

        const unsigned char* gR = rP[cur];               // g(t), warp-private rows
        const uint32_t      xRb = rB[cur ^ 1];           // X region
        const unsigned char* xR = rP[cur ^ 1];
        const float*        psm = (const float*)pP[cur];

        // ---- X build: x = g + 0.1*g^3/(||g^3||+eps)*||g||, bf16 hi/lo ----
        {
            float gv[32];
            const uint4* grow = (const uint4*)(gR + tid * RSTR);
            #pragma unroll
            for (int q = 0; q < 8; q++) {
                uint4 v = grow[q];
                gv[4*q+0] = __uint_as_float(v.x); gv[4*q+1] = __uint_as_float(v.y);
                gv[4*q+2] = __uint_as_float(v.z); gv[4*q+3] = __uint_as_float(v.w);
            }
            float gn2 = 0.f, cn2 = 0.f;
            #pragma unroll
            for (int i = 0; i < 32; i++) {
                float q = gv[i] * gv[i];
                gn2 += q;
                float c3 = q * gv[i];
                cn2 = fmaf(c3, c3, cn2);
            }
            const float tt = PATW * sqrtf(gn2) / (sqrtf(cn2) + EPSF);
            uint32_t xh[16], xl[16];
            #pragma unroll
            for (int i = 0; i < 16; i++) {
                float x0 = fmaf(tt * gv[2*i]   * gv[2*i],   gv[2*i],   gv[2*i]);
                float x1 = fmaf(tt * gv[2*i+1] * gv[2*i+1], gv[2*i+1], gv[2*i+1]);
                uint32_t p = packbf2(x0, x1);
                xh[i] = p;
                float l0 = x0 - __uint_as_float(p << 16);
                float l1 = x1 - __uint_as_float(p & 0xFFFF0000u);
                xl[i] = packbf2(l0, l1);
            }
            uint4* xr = (uint4*)(xR + tid * RSTR);
            #pragma unroll
            for (int j = 0; j < 4; j++)
                xr[j] = make_uint4(xh[4*j], xh[4*j+1], xh[4*j+2], xh[4*j+3]);
            #pragma unroll
            for (int j = 0; j < 4; j++)
                xr[4 + j] = make_uint4(xl[4*j], xl[4*j+1], xl[4*j+2], xl[4*j+3]);
        }
        __syncwarp();    // cross-lane X visibility for ldmatrix

        // ---- A fragments (xh cols 0..31, xl cols 32..63) ----
        uint32_t Ah[2][2][4], Al[2][2][4];
        #pragma unroll
        for (int mt = 0; mt < 2; mt++)
            #pragma unroll
            for (int ks = 0; ks < 2; ks++) {
                uint32_t base = xRb + (uint32_t)(m0 + mt*16 + (lane & 15)) * RSTR
                              + ((lane >> 4) << 4);
                ldm4(Ah[mt][ks], base + (uint32_t)(ks*16) * 2);
                ldm4(Al[mt][ks], base + (uint32_t)(32 + ks*16) * 2);
            }
        // ldmatrix.sync is warp-synchronous: all X reads complete here.

        // ---- prefetch tile t+GRIDC into X region (dead now) ----
        {
            int tn = t + GRIDC;
            if (tn < NTILES) {
                const float* src = grid + (size_t)tn * 4096 + m0 * 32;
                #pragma unroll
                for (int c = 0; c < 8; c++) {
                    int flat = lane + 32 * c;
                    int row = flat >> 3, q = flat & 7;
                    cpa16(xRb + (uint32_t)(m0 + row) * RSTR + q * 16, src + flat * 4);
                }
                if (lane < 8)
                    cpa16(pB[cur ^ 1] + (uint32_t)(m0 + lane * 4) * 4,
                          pot + (size_t)tn * 128 + m0 + lane * 4);
            }
            asm volatile("cp.async.commit_group;");
        }

        // ---- B1 wh fragments ----
        uint32_t Bf[2][8][2];
        #pragma unroll
        for (int ks = 0; ks < 2; ks++)
            #pragma unroll
            for (int np = 0; np < 4; np++) {
                uint32_t a = b1_b + (uint32_t)(np*16 + ((lane>>4)<<3) + (lane&7)) * (B1STR*2)
                           + (uint32_t)(ks*16)*2 + (((lane>>3)&1) << 4);
                ldm4(&Bf[ks][2*np][0], a);
            }

        // ---- C1 init: b1[n] + pot[m]*W1[32][n] ----
        float C[2][8][4];
        const int nb = (lane & 3) * 2;
        float pv[2][2];
        #pragma unroll
        for (int mt = 0; mt < 2; mt++) {
            pv[mt][0] = psm[m0 + mt*16 + (lane >> 2)];
            pv[mt][1] = psm[m0 + mt*16 + (lane >> 2) + 8];
        }
        #pragma unroll
        for (int nt = 0; nt < 8; nt++) {
            int n = nt*8 + nb;
            float bb0 = b1s[n], bb1 = b1s[n+1], w0 = w1p[n], w1v = w1p[n+1];
            #pragma unroll
            for (int mt = 0; mt < 2; mt++) {
                C[mt][nt][0] = fmaf(pv[mt][0], w0,  bb0);
                C[mt][nt][1] = fmaf(pv[mt][0], w1v, bb1);
                C[mt][nt][2] = fmaf(pv[mt][1], w0,  bb0);
                C[mt][nt][3] = fmaf(pv[mt][1], w1v, bb1);
            }
        }

        // ---- GEMM1: xh*wh + xl*wh, then xh*wl ----
        #pragma unroll
        for (int ks = 0; ks < 2; ks++)
            #pragma unroll
            for (int mt = 0; mt < 2; mt++)
                #pragma unroll
                for (int nt = 0; nt < 8; nt++)
                    mma16816(C[mt][nt], Ah[mt][ks], Bf[ks][nt]);
        #pragma unroll
        for (int ks = 0; ks < 2; ks++)
            #pragma unroll
            for (int mt = 0; mt < 2; mt++)
                #pragma unroll
                for (int nt = 0; nt < 8; nt++)
                    mma16816(C[mt][nt], Al[mt][ks], Bf[ks][nt]);
        #pragma unroll
        for (int ks = 0; ks < 2; ks++)
            #pragma unroll
            for (int np = 0; np < 4; np++) {
                uint32_t a = b1_b + (uint32_t)(np*16 + ((lane>>4)<<3) + (lane&7)) * (B1STR*2)
                           + (uint32_t)(32 + ks*16)*2 + (((lane>>3)&1) << 4);
                ldm4(&Bf[ks][2*np][0], a);
            }
        #pragma unroll
        for (int ks = 0; ks < 2; ks++)
            #pragma unroll
            for (int mt = 0; mt < 2; mt++)
                #pragma unroll
                for (int nt = 0; nt < 8; nt++)
                    mma16816(C[mt][nt], Ah[mt][ks], Bf[ks][nt]);

        // ---- relu + split -> A2 fragments ----
        uint32_t Hh[2][4][4], Hl[2][4][4];
        #pragma unroll
        for (int mt = 0; mt < 2; mt++)
            #pragma unroll
            for (int ks = 0; ks < 4; ks++)
                #pragma unroll
                for (int q = 0; q < 4; q++) {
                    int nt = 2*ks + (q >> 1);
                    float hA = fmaxf(C[mt][nt][(q & 1) * 2],     0.f);
                    float hB = fmaxf(C[mt][nt][(q & 1) * 2 + 1], 0.f);
                    uint32_t p = packbf2(hA, hB);
                    Hh[mt][ks][q] = p;
                    float lA = hA - __uint_as_float(p << 16);
                    float lB = hB - __uint_as_float(p & 0xFFFF0000u);
                    Hl[mt][ks][q] = packbf2(lA, lB);
                }

        // ---- GEMM2: hh*w2h + hl*w2h, then hh*w2l ----
        float C2[2][4][4];
        #pragma unroll
        for (int mt = 0; mt < 2; mt++)
            #pragma unroll
            for (int nt = 0; nt < 4; nt++)
                #pragma unroll
                for (int q = 0; q < 4; q++) C2[mt][nt][q] = 0.f;

        uint32_t B2f[4][2];
        #pragma unroll
        for (int ks = 0; ks < 4; ks++) {
            #pragma unroll
            for (int np = 0; np < 2; np++) {
                uint32_t a = b2_b + (uint32_t)(np*16 + ((lane>>4)<<3) + (lane&7)) * (B2STR*2)
                           + (uint32_t)(ks*16)*2 + (((lane>>3)&1) << 4);
                ldm4(&B2f[2*np][0], a);
            }
            #pragma unroll
            for (int mt = 0; mt < 2; mt++)
                #pragma unroll
                for (int nt = 0; nt < 4; nt++) {
                    mma16816(C2[mt][nt], Hh[mt][ks], B2f[nt]);
                    mma16816(C2[mt][nt], Hl[mt][ks], B2f[nt]);
                }
        }
        #pragma unroll
        for (int ks = 0; ks < 4; ks++) {
            #pragma unroll
            for (int np = 0; np < 2; np++) {
                uint32_t a = b2_b + (uint32_t)(np*16 + ((lane>>4)<<3) + (lane&7)) * (B2STR*2)
                           + (uint32_t)(64 + ks*16)*2 + (((lane>>3)&1) << 4);
                ldm4(&B2f[2*np][0], a);
            }
            #pragma unroll
            for (int mt = 0; mt < 2; mt++)
                #pragma unroll
                for (int nt = 0; nt < 4; nt++)
                    mma16816(C2[mt][nt], Hh[mt][ks], B2f[nt]);
        }

        // ---- epilogue: out = C2 + b2 + alpha*g ----
        {
            float* outb = out + (size_t)t * 4096;
            #pragma unroll
            for (int mt = 0; mt < 2; mt++) {
                int r0 = m0 + mt*16 + (lane >> 2);
                int r1 = r0 + 8;
                const float* g0 = (const float*)(gR + r0 * RSTR);
                const float* g1 = (const float*)(gR + r1 * RSTR);
                #pragma unroll
                for (int nt = 0; nt < 4; nt++) {
                    int n = nt*8 + nb;
                    float bb0 = b2s[n], bb1 = b2s[n+1];
                    float2 o0, o1;
                    o0.x = fmaf(ALPHAF, g0[n],     C2[mt][nt][0] + bb0);
                    o0.y = fmaf(ALPHAF, g0[n + 1], C2[mt][nt][1] + bb1);
                    o1.x = fmaf(ALPHAF, g1[n],     C2[mt][nt][2] + bb0);
                    o1.y = fmaf(ALPHAF, g1[n + 1], C2[mt][nt][3] + bb1);
                    *(float2*)(outb + r0*32 + n) = o0;
                    *(float2*)(outb + r1*32 + n) = o1;
                }
            }
        }
        cur ^= 1;
    }
}

extern "C" void kernel_launch(void* const* d_in, const int* in_sizes, int n_in,
                              void* d_out, int out_size) {
    const float* grid = (const float*)d_in[0];
    const float* pot  = (const float*)d_in[1];
    const float* W1   = (const float*)d_in[2];
    const float* b1   = (const float*)d_in[3];
    const float* W2   = (const float*)d_in[4];
    const float* b2   = (const float*)d_in[5];
    float* out = (float*)d_out;

    cudaFuncSetAttribute(be_mma, cudaFuncAttributeMaxDynamicSharedMemorySize, SMEMSZ);
    be_mma<<<GRIDC, 128, SMEMSZ>>>(grid, pot, W1, b1, W2, b2, out);
}

// round 11
// speedup vs baseline: 1.8398x; 1.2391x over previous
#include <cuda_runtime.h>
#include <cstdint>

#define ALPHAF 0.3f
#define EPSF   1e-8f
#define PATW   0.1f

#define GRIDC  608          // 152 SMs x 4 CTAs, persistent
#define NTILES 8192

// ---- dynamic smem layout (bytes) ----
#define RSTR   144          // region row stride: g fp32 (128B)+pad / X 64 halfs+pad
#define O_R0   0            // region 0: 128 x 144 = 18432
#define O_R1   18432        // region 1: 18432 (init: raw W1 @ +0, raw W2 @ +8704)
#define O_B1   36864        // B1 image: 64 rows x 40 halfs = 5120
#define O_B2   41984        // B2 image: 32 rows x 72 halfs = 4608
#define O_P0   46592        // pot buf 0: 128 f32
#define O_P1   47104        // pot buf 1
#define O_B1S  47616        // b1: 64 f32
#define O_W1P  47872        // W1[32][:]: 64 f32
#define O_B2S  48128        // b2: 32 f32
#define SMEMSZ 48256

#define B1STR 40    // halfs (80B rows: 64B data + 16B pad, conflict-free)
#define B2STR 72    // halfs (144B rows: 128B data + 16B pad)

static __device__ __forceinline__ void ldm4(uint32_t* r, uint32_t addr) {
    asm volatile("ldmatrix.sync.aligned.m8n8.x4.shared.b16 {%0,%1,%2,%3}, [%4];"
                 : "=r"(r[0]), "=r"(r[1]), "=r"(r[2]), "=r"(r[3]) : "r"(addr));
}
static __device__ __forceinline__ void mma16816(float* c, const uint32_t* a, const uint32_t* b) {
    asm volatile(
        "mma.sync.aligned.m16n8k16.row.col.f32.f16.f16.f32 "
        "{%0,%1,%2,%3},{%4,%5,%6,%7},{%8,%9},{%0,%1,%2,%3};"
        : "+f"(c[0]), "+f"(c[1]), "+f"(c[2]), "+f"(c[3])
        : "r"(a[0]), "r"(a[1]), "r"(a[2]), "r"(a[3]), "r"(b[0]), "r"(b[1]));
}
// pack two fp32 -> f16x2 (round-to-nearest)
static __device__ __forceinline__ uint32_t packh2(float lo, float hi) {
    uint32_t r;
    asm("{\n\t.reg .f16 l, h;\n\t"
        "cvt.rn.f16.f32 l, %1;\n\t"
        "cvt.rn.f16.f32 h, %2;\n\t"
        "mov.b32 %0, {l, h};\n\t}"
        : "=r"(r) : "f"(lo), "f"(hi));
    return r;
}
static __device__ __forceinline__ float h2f_lo(uint32_t p) {
    float f;
    asm("{\n\t.reg .f16 l, h;\n\tmov.b32 {l, h}, %1;\n\tcvt.f32.f16 %0, l;\n\t}"
        : "=f"(f) : "r"(p));
    return f;
}
static __device__ __forceinline__ float h2f_hi(uint32_t p) {
    float f;
    asm("{\n\t.reg .f16 l, h;\n\tmov.b32 {l, h}, %1;\n\tcvt.f32.f16 %0, h;\n\t}"
        : "=f"(f) : "r"(p));
    return f;
}
static __device__ __forceinline__ void cpa16(uint32_t dst, const void* src) {
    asm volatile("cp.async.ca.shared.global [%0], [%1], 16;" :: "r"(dst), "l"(src));
}

__global__ void __launch_bounds__(128, 4)
be_mma(const float* __restrict__ grid, const float* __restrict__ pot,
       const float* __restrict__ W1,   const float* __restrict__ b1,
       const float* __restrict__ W2,   const float* __restrict__ b2,
       float* __restrict__ out)
{
    extern __shared__ __align__(16) unsigned char sm[];
    float* b1s = (float*)(sm + O_B1S);
    float* w1p = (float*)(sm + O_W1P);
    float* b2s = (float*)(sm + O_B2S);
    unsigned short* img1 = (unsigned short*)(sm + O_B1);
    unsigned short* img2 = (unsigned short*)(sm + O_B2);

    const int tid  = threadIdx.x;
    const int lane = tid & 31;
    const int w    = tid >> 5;
    const int m0   = w * 32;

    const uint32_t r0b  = (uint32_t)__cvta_generic_to_shared(sm + O_R0);
    const uint32_t r1b  = (uint32_t)__cvta_generic_to_shared(sm + O_R1);
    const uint32_t b1_b = (uint32_t)__cvta_generic_to_shared(sm + O_B1);
    const uint32_t b2_b = (uint32_t)__cvta_generic_to_shared(sm + O_B2);
    const uint32_t p0b  = (uint32_t)__cvta_generic_to_shared(sm + O_P0);
    const uint32_t p1b  = (uint32_t)__cvta_generic_to_shared(sm + O_P1);

    // ===== prologue: prefetch tile-0 warp slice FIRST (into region 0) =====
    {
        const float* src = grid + (size_t)blockIdx.x * 4096 + m0 * 32;
        #pragma unroll
        for (int c = 0; c < 8; c++) {
            int flat = lane + 32 * c;                    // 16B chunks
            int row = flat >> 3, q = flat & 7;
            cpa16(r0b + (uint32_t)(m0 + row) * RSTR + q * 16, src + flat * 4);
        }
        if (lane < 8)
            cpa16(p0b + (uint32_t)(m0 + lane * 4) * 4,
                  pot + (size_t)blockIdx.x * 128 + m0 + lane * 4);
        asm volatile("cp.async.commit_group;");
    }

    // ===== one-time weight build (raw staging entirely inside region 1) ====
    {
        float* rw1 = (float*)(sm + O_R1);          // 2112 f32 (8448 B)
        float* rw2 = (float*)(sm + O_R1 + 8704);   // 2048 f32 (8192 B)
        #pragma unroll
        for (int i = tid; i < 2112; i += 128) rw1[i] = W1[i];
        #pragma unroll
        for (int i = tid; i < 2048; i += 128) rw2[i] = W2[i];
        if (tid < 64) b1s[tid] = b1[tid];
        if (tid < 32) b2s[tid] = b2[tid];
        __syncthreads();

        if (tid < 64) {                     // W1 column n = tid -> fp16, k<32
            const int n = tid;
            uint32_t ph[16];
            #pragma unroll
            for (int kk = 0; kk < 16; kk++)
                ph[kk] = packh2(rw1[(2*kk)*64 + n], rw1[(2*kk+1)*64 + n]);
            uint4* dh = (uint4*)(img1 + n * B1STR);
            #pragma unroll
            for (int q = 0; q < 4; q++)
                dh[q] = make_uint4(ph[4*q], ph[4*q+1], ph[4*q+2], ph[4*q+3]);
            w1p[n] = rw1[32 * 64 + n];
        } else {                            // W2 column n2, K-half kh -> fp16
            const int n2 = (tid - 64) >> 1;
            const int kh = (tid & 1) * 32;
            uint32_t ph[16];
            #pragma unroll
            for (int kk = 0; kk < 16; kk++) {
                int k = kh + 2 * kk;
                ph[kk] = packh2(rw2[k*32 + n2], rw2[(k+1)*32 + n2]);
            }
            uint4* dh = (uint4*)(img2 + n2 * B2STR + kh);
            #pragma unroll
            for (int q = 0; q < 4; q++)
                dh[q] = make_uint4(ph[4*q], ph[4*q+1], ph[4*q+2], ph[4*q+3]);
        }
        __syncthreads();
    }

    // ===== persistent per-warp tile loop ====================================
    const uint32_t rB[2] = { r0b, r1b };
    const uint32_t pB[2] = { p0b, p1b };
    const unsigned char* const rP[2] = { sm + O_R0, sm + O_R1 };
    const unsigned char* const pP[2] = { sm + O_P0, sm + O_P1 };

    int cur = 0;
    for (int t = blockIdx.x; t < NTILES; t += GRIDC) {
        asm volatile("cp.async.wait_group 0;");          // own prefetch landed

        const unsigned char* gR = rP[cur];               // g(t), warp-private rows
        const uint32_t      xRb = rB[cur ^ 1];           // X region
        const unsigned char* xR = rP[cur ^ 1];
        const float*        psm = (const float*)pP[cur];

        // ---- X build: x = g + 0.1*g^3/(||g^3||+eps)*||g||, fp16 hi/lo ----
        {
            float gv[32];
            const uint4* grow = (const uint4*)(gR + tid * RSTR);
            #pragma unroll
            for (int q = 0; q < 8; q++) {
                uint4 v = grow[q];
                gv[4*q+0] = __uint_as_float(v.x); gv[4*q+1] = __uint_as_float(v.y);
                gv[4*q+2] = __uint_as_float(v.z); gv[4*q+3] = __uint_as_float(v.w);
            }
            float gn2 = 0.f, cn2 = 0.f;
            #pragma unroll
            for (int i = 0; i < 32; i++) {
                float q = gv[i] * gv[i];
                gn2 += q;
                float c3 = q * gv[i];
                cn2 = fmaf(c3, c3, cn2);
            }
            const float tt = PATW * sqrtf(gn2) / (sqrtf(cn2) + EPSF);
            uint32_t xh[16], xl[16];
            #pragma unroll
            for (int i = 0; i < 16; i++) {
                float x0 = fmaf(tt * gv[2*i]   * gv[2*i],   gv[2*i],   gv[2*i]);
                float x1 = fmaf(tt * gv[2*i+1] * gv[2*i+1], gv[2*i+1], gv[2*i+1]);
                uint32_t p = packh2(x0, x1);
                xh[i] = p;
                xl[i] = packh2(x0 - h2f_lo(p), x1 - h2f_hi(p));
            }
            uint4* xr = (uint4*)(xR + tid * RSTR);
            #pragma unroll
            for (int j = 0; j < 4; j++)
                xr[j] = make_uint4(xh[4*j], xh[4*j+1], xh[4*j+2], xh[4*j+3]);
            #pragma unroll
            for (int j = 0; j < 4; j++)
                xr[4 + j] = make_uint4(xl[4*j], xl[4*j+1], xl[4*j+2], xl[4*j+3]);
        }
        __syncwarp();    // cross-lane X visibility for ldmatrix

        // ---- A fragments (xh cols 0..31, xl cols 32..63) ----
        uint32_t Ah[2][2][4], Al[2][2][4];
        #pragma unroll
        for (int mt = 0; mt < 2; mt++)
            #pragma unroll
            for (int ks = 0; ks < 2; ks++) {
                uint32_t base = xRb + (uint32_t)(m0 + mt*16 + (lane & 15)) * RSTR
                              + ((lane >> 4) << 4);
                ldm4(Ah[mt][ks], base + (uint32_t)(ks*16) * 2);
                ldm4(Al[mt][ks], base + (uint32_t)(32 + ks*16) * 2);
            }
        // ldmatrix.sync is warp-synchronous: all X reads complete here.

        // ---- prefetch tile t+GRIDC into X region (dead now) ----
        {
            int tn = t + GRIDC;
            if (tn < NTILES) {
                const float* src = grid + (size_t)tn * 4096 + m0 * 32;
                #pragma unroll
                for (int c = 0; c < 8; c++) {
                    int flat = lane + 32 * c;
                    int row = flat >> 3, q = flat & 7;
                    cpa16(xRb + (uint32_t)(m0 + row) * RSTR + q * 16, src + flat * 4);
                }
                if (lane < 8)
                    cpa16(pB[cur ^ 1] + (uint32_t)(m0 + lane * 4) * 4,
                          pot + (size_t)tn * 128 + m0 + lane * 4);
            }
            asm volatile("cp.async.commit_group;");
        }

        // ---- B1 fragments (single fp16 image, loaded once) ----
        uint32_t Bf[2][8][2];
        #pragma unroll
        for (int ks = 0; ks < 2; ks++)
            #pragma unroll
            for (int np = 0; np < 4; np++) {
                uint32_t a = b1_b + (uint32_t)(np*16 + ((lane>>4)<<3) + (lane&7)) * (B1STR*2)
                           + (uint32_t)(ks*16)*2 + (((lane>>3)&1) << 4);
                ldm4(&Bf[ks][2*np][0], a);
            }

        // ---- C1 init: b1[n] + pot[m]*W1[32][n] (fp32 exact) ----
        float C[2][8][4];
        const int nb = (lane & 3) * 2;
        float pv[2][2];
        #pragma unroll
        for (int mt = 0; mt < 2; mt++) {
            pv[mt][0] = psm[m0 + mt*16 + (lane >> 2)];
            pv[mt][1] = psm[m0 + mt*16 + (lane >> 2) + 8];
        }
        #pragma unroll
        for (int nt = 0; nt < 8; nt++) {
            int n = nt*8 + nb;
            float bb0 = b1s[n], bb1 = b1s[n+1], w0 = w1p[n], w1v = w1p[n+1];
            #pragma unroll
            for (int mt = 0; mt < 2; mt++) {
                C[mt][nt][0] = fmaf(pv[mt][0], w0,  bb0);
                C[mt][nt][1] = fmaf(pv[mt][0], w1v, bb1);
                C[mt][nt][2] = fmaf(pv[mt][1], w0,  bb0);
                C[mt][nt][3] = fmaf(pv[mt][1], w1v, bb1);
            }
        }

        // ---- GEMM1: xh*w + xl*w (2 passes, no B reload) ----
        #pragma unroll
        for (int ks = 0; ks < 2; ks++)
            #pragma unroll
            for (int mt = 0; mt < 2; mt++)
                #pragma unroll
                for (int nt = 0; nt < 8; nt++)
                    mma16816(C[mt][nt], Ah[mt][ks], Bf[ks][nt]);
        #pragma unroll
        for (int ks = 0; ks < 2; ks++)
            #pragma unroll
            for (int mt = 0; mt < 2; mt++)
                #pragma unroll
                for (int nt = 0; nt < 8; nt++)
                    mma16816(C[mt][nt], Al[mt][ks], Bf[ks][nt]);

        // ---- relu + fp16 2-term split -> A2 fragments ----
        uint32_t Hh[2][4][4], Hl[2][4][4];
        #pragma unroll
        for (int mt = 0; mt < 2; mt++)
            #pragma unroll
            for (int ks = 0; ks < 4; ks++)
                #pragma unroll
                for (int q = 0; q < 4; q++) {
                    int nt = 2*ks + (q >> 1);
                    float hA = fmaxf(C[mt][nt][(q & 1) * 2],     0.f);
                    float hB = fmaxf(C[mt][nt][(q & 1) * 2 + 1], 0.f);
                    uint32_t p = packh2(hA, hB);
                    Hh[mt][ks][q] = p;
                    Hl[mt][ks][q] = packh2(hA - h2f_lo(p), hB - h2f_hi(p));
                }

        // ---- GEMM2: hh*w2 + hl*w2 (single fp16 image) ----
        float C2[2][4][4];
        #pragma unroll
        for (int mt = 0; mt < 2; mt++)
            #pragma unroll
            for (int nt = 0; nt < 4; nt++)
                #pragma unroll
                for (int q = 0; q < 4; q++) C2[mt][nt][q] = 0.f;

        uint32_t B2f[4][2];
        #pragma unroll
        for (int ks = 0; ks < 4; ks++) {
            #pragma unroll
            for (int np = 0; np < 2; np++) {
                uint32_t a = b2_b + (uint32_t)(np*16 + ((lane>>4)<<3) + (lane&7)) * (B2STR*2)
                           + (uint32_t)(ks*16)*2 + (((lane>>3)&1) << 4);
                ldm4(&B2f[2*np][0], a);
            }
            #pragma unroll
            for (int mt = 0; mt < 2; mt++)
                #pragma unroll
                for (int nt = 0; nt < 4; nt++) {
                    mma16816(C2[mt][nt], Hh[mt][ks], B2f[nt]);
                    mma16816(C2[mt][nt], Hl[mt][ks], B2f[nt]);
                }
        }

        // ---- epilogue: out = C2 + b2 + alpha*g ----
        {
            float* outb = out + (size_t)t * 4096;
            #pragma unroll
            for (int mt = 0; mt < 2; mt++) {
                int r0 = m0 + mt*16 + (lane >> 2);
                int r1 = r0 + 8;
                const float* g0 = (const float*)(gR + r0 * RSTR);
                const float* g1 = (const float*)(gR + r1 * RSTR);
                #pragma unroll
                for (int nt = 0; nt < 4; nt++) {
                    int n = nt*8 + nb;
                    float bb0 = b2s[n], bb1 = b2s[n+1];
                    float2 o0, o1;
                    o0.x = fmaf(ALPHAF, g0[n],     C2[mt][nt][0] + bb0);
                    o0.y = fmaf(ALPHAF, g0[n + 1], C2[mt][nt][1] + bb1);
                    o1.x = fmaf(ALPHAF, g1[n],     C2[mt][nt][2] + bb0);
                    o1.y = fmaf(ALPHAF, g1[n + 1], C2[mt][nt][3] + bb1);
                    *(float2*)(outb + r0*32 + n) = o0;
                    *(float2*)(outb + r1*32 + n) = o1;
                }
            }
        }
        cur ^= 1;
    }
}

extern "C" void kernel_launch(void* const* d_in, const int* in_sizes, int n_in,
                              void* d_out, int out_size) {
    const float* grid = (const float*)d_in[0];
    const float* pot  = (const float*)d_in[1];
    const float* W1   = (const float*)d_in[2];
    const float* b1   = (const float*)d_in[3];
    const float* W2   = (const float*)d_in[4];
    const float* b2   = (const float*)d_in[5];
    float* out = (float*)d_out;

    cudaFuncSetAttribute(be_mma, cudaFuncAttributeMaxDynamicSharedMemorySize, SMEMSZ);
    be_mma<<<GRIDC, 128, SMEMSZ>>>(grid, pot, W1, b1, W2, b2, out);
}

// round 12
// speedup vs baseline: 1.8489x; 1.0049x over previous
#include <cuda_runtime.h>
#include <cstdint>

#define ALPHAF 0.3f
#define EPSF   1e-8f
#define PATW   0.1f

#define GRIDC  608          // 152 SMs x 4 CTAs, persistent
#define NTILES 8192

// ---- dynamic smem layout (bytes) ----
// g buffers are stored in FRAGMENT order: per warp 4096B = 16 slots x 256B.
// slot s = (mt*4 + j)*2 + h  holds the 8x8 fp32 block rows (m0+mt*16+h*8..+7),
// cols (j*8..j*8+7), entry (r&7, colpair p) at offset (r*4+p)*8 (lane-major).
#define O_G0   0        // g frag buf 0: 4 warps x 4096 = 16384
#define O_G1   16384    // g frag buf 1: 16640 (incl. 256B pad; raw-W staging at init)
#define O_B1   33024    // B1 image: 64 rows x 40 halfs = 5120
#define O_B2   38144    // B2 image: 32 rows x 72 halfs = 4608
#define O_P0   42752    // pot buf 0: 128 f32
#define O_P1   43264    // pot buf 1
#define O_B1S  43776    // b1: 64 f32
#define O_W1P  44032    // W1[32][:]: 64 f32
#define O_B2S  44288    // b2: 32 f32
#define SMEMSZ 44416

#define B1STR 40    // halfs (80B rows, conflict-free)
#define B2STR 72    // halfs (144B rows)

static __device__ __forceinline__ void ldm4(uint32_t* r, uint32_t addr) {
    asm volatile("ldmatrix.sync.aligned.m8n8.x4.shared.b16 {%0,%1,%2,%3}, [%4];"
                 : "=r"(r[0]), "=r"(r[1]), "=r"(r[2]), "=r"(r[3]) : "r"(addr));
}
static __device__ __forceinline__ void mma16816(float* c, const uint32_t* a, const uint32_t* b) {
    asm volatile(
        "mma.sync.aligned.m16n8k16.row.col.f32.f16.f16.f32 "
        "{%0,%1,%2,%3},{%4,%5,%6,%7},{%8,%9},{%0,%1,%2,%3};"
        : "+f"(c[0]), "+f"(c[1]), "+f"(c[2]), "+f"(c[3])
        : "r"(a[0]), "r"(a[1]), "r"(a[2]), "r"(a[3]), "r"(b[0]), "r"(b[1]));
}
static __device__ __forceinline__ uint32_t packh2(float lo, float hi) {
    uint32_t r;
    asm("{\n\t.reg .f16 l, h;\n\t"
        "cvt.rn.f16.f32 l, %1;\n\t"
        "cvt.rn.f16.f32 h, %2;\n\t"
        "mov.b32 %0, {l, h};\n\t}"
        : "=r"(r) : "f"(lo), "f"(hi));
    return r;
}
static __device__ __forceinline__ float h2f_lo(uint32_t p) {
    float f;
    asm("{\n\t.reg .f16 l, h;\n\tmov.b32 {l, h}, %1;\n\tcvt.f32.f16 %0, l;\n\t}"
        : "=f"(f) : "r"(p));
    return f;
}
static __device__ __forceinline__ float h2f_hi(uint32_t p) {
    float f;
    asm("{\n\t.reg .f16 l, h;\n\tmov.b32 {l, h}, %1;\n\tcvt.f32.f16 %0, h;\n\t}"
        : "=f"(f) : "r"(p));
    return f;
}
static __device__ __forceinline__ void cpa16(uint32_t dst, const void* src) {
    asm volatile("cp.async.ca.shared.global [%0], [%1], 16;" :: "r"(dst), "l"(src));
}

__global__ void __launch_bounds__(128, 4)
be_mma(const float* __restrict__ grid, const float* __restrict__ pot,
       const float* __restrict__ W1,   const float* __restrict__ b1,
       const float* __restrict__ W2,   const float* __restrict__ b2,
       float* __restrict__ out)
{
    extern __shared__ __align__(16) unsigned char sm[];
    float* b1s = (float*)(sm + O_B1S);
    float* w1p = (float*)(sm + O_W1P);
    float* b2s = (float*)(sm + O_B2S);
    unsigned short* img1 = (unsigned short*)(sm + O_B1);
    unsigned short* img2 = (unsigned short*)(sm + O_B2);

    const int tid  = threadIdx.x;
    const int lane = tid & 31;
    const int w    = tid >> 5;
    const int m0   = w * 32;

    const uint32_t g0b  = (uint32_t)__cvta_generic_to_shared(sm + O_G0) + w * 4096;
    const uint32_t g1b  = (uint32_t)__cvta_generic_to_shared(sm + O_G1) + w * 4096;
    const uint32_t b1_b = (uint32_t)__cvta_generic_to_shared(sm + O_B1);
    const uint32_t b2_b = (uint32_t)__cvta_generic_to_shared(sm + O_B2);
    const uint32_t p0b  = (uint32_t)__cvta_generic_to_shared(sm + O_P0);
    const uint32_t p1b  = (uint32_t)__cvta_generic_to_shared(sm + O_P1);

    // per-lane constants for the fragment-order cp.async scatter
    const int cc_c  = lane & 7;             // 16B col-chunk within row
    const int cc_j  = cc_c >> 1;
    const int cc_p0 = (cc_c & 1) * 2;
    const int cc_rb = lane >> 3;            // row base (0..3), +4 per chunk

    // ===== prologue: prefetch tile-0 warp slice into g buf 0 (frag order) ==
    {
        const float* src = grid + (size_t)blockIdx.x * 4096 + m0 * 32;
        #pragma unroll
        for (int cc = 0; cc < 8; cc++) {
            int f   = lane + 32 * cc;
            int row = cc_rb + 4 * cc;
            int mt = row >> 4, h = (row >> 3) & 1, rr = row & 7;
            uint32_t dst = g0b + (uint32_t)(((mt*4 + cc_j)*2 + h)*256 + (rr*4 + cc_p0)*8);
            cpa16(dst, src + f * 4);
        }
        if (lane < 8)
            cpa16(p0b + (uint32_t)(m0 + lane * 4) * 4,
                  pot + (size_t)blockIdx.x * 128 + m0 + lane * 4);
        asm volatile("cp.async.commit_group;");
    }

    // ===== one-time weight build (raw staging inside g-buf-1 region) =======
    {
        float* rw1 = (float*)(sm + O_G1);          // 2112 f32 (8448 B)
        float* rw2 = (float*)(sm + O_G1 + 8448);   // 2048 f32 (8192 B)
        #pragma unroll
        for (int i = tid; i < 2112; i += 128) rw1[i] = W1[i];
        #pragma unroll
        for (int i = tid; i < 2048; i += 128) rw2[i] = W2[i];
        if (tid < 64) b1s[tid] = b1[tid];
        if (tid < 32) b2s[tid] = b2[tid];
        __syncthreads();

        if (tid < 64) {                     // W1 column n = tid -> fp16
            const int n = tid;
            uint32_t ph[16];
            #pragma unroll
            for (int kk = 0; kk < 16; kk++)
                ph[kk] = packh2(rw1[(2*kk)*64 + n], rw1[(2*kk+1)*64 + n]);
            uint4* dh = (uint4*)(img1 + n * B1STR);
            #pragma unroll
            for (int q = 0; q < 4; q++)
                dh[q] = make_uint4(ph[4*q], ph[4*q+1], ph[4*q+2], ph[4*q+3]);
            w1p[n] = rw1[32 * 64 + n];
        } else {                            // W2 column n2, K-half kh -> fp16
            const int n2 = (tid - 64) >> 1;
            const int kh = (tid & 1) * 32;
            uint32_t ph[16];
            #pragma unroll
            for (int kk = 0; kk < 16; kk++) {
                int k = kh + 2 * kk;
                ph[kk] = packh2(rw2[k*32 + n2], rw2[(k+1)*32 + n2]);
            }
            uint4* dh = (uint4*)(img2 + n2 * B2STR + kh);
            #pragma unroll
            for (int q = 0; q < 4; q++)
                dh[q] = make_uint4(ph[4*q], ph[4*q+1], ph[4*q+2], ph[4*q+3]);
        }
        __syncthreads();
    }

    // ===== persistent per-warp tile loop ====================================
    const uint32_t gB[2] = { g0b, g1b };
    const uint32_t pB[2] = { p0b, p1b };
    const unsigned char* const pP[2] = { sm + O_P0, sm + O_P1 };

    int cur = 0;
    for (int t = blockIdx.x; t < NTILES; t += GRIDC) {
        // ---- prefetch tile t+GRIDC into buf cur^1 (overlaps whole iter) ----
        {
            int tn = t + GRIDC;
            if (tn < NTILES) {
                const float* src = grid + (size_t)tn * 4096 + m0 * 32;
                uint32_t db = gB[cur ^ 1];
                #pragma unroll
                for (int cc = 0; cc < 8; cc++) {
                    int f   = lane + 32 * cc;
                    int row = cc_rb + 4 * cc;
                    int mt = row >> 4, h = (row >> 3) & 1, rr = row & 7;
                    uint32_t dst = db + (uint32_t)(((mt*4 + cc_j)*2 + h)*256 + (rr*4 + cc_p0)*8);
                    cpa16(dst, src + f * 4);
                }
                if (lane < 8)
                    cpa16(pB[cur ^ 1] + (uint32_t)(m0 + lane * 4) * 4,
                          pot + (size_t)tn * 128 + m0 + lane * 4);
            }
            asm volatile("cp.async.commit_group;");
            asm volatile("cp.async.wait_group 1;");      // tile t's data ready
        }

        const uint32_t gb = gB[cur];
        const float* psm  = (const float*)pP[cur];

        // ---- load g fragments (conflict-free LDS.64) ----
        float2 G[2][4][2];
        #pragma unroll
        for (int mt = 0; mt < 2; mt++)
            #pragma unroll
            for (int j = 0; j < 4; j++)
                #pragma unroll
                for (int h = 0; h < 2; h++) {
                    uint32_t a = gb + (uint32_t)((((mt*4 + j)*2 + h)*256) + lane*8);
                    float2 v;
                    asm volatile("ld.shared.v2.f32 {%0,%1}, [%2];"
                                 : "=f"(v.x), "=f"(v.y) : "r"(a));
                    G[mt][j][h] = v;
                }

        // ---- row norms via quad shfl (lanes lane&3 hold the 4 col groups) --
        float pg[2][2] = {{0.f,0.f},{0.f,0.f}}, pc[2][2] = {{0.f,0.f},{0.f,0.f}};
        #pragma unroll
        for (int mt = 0; mt < 2; mt++)
            #pragma unroll
            for (int h = 0; h < 2; h++)
                #pragma unroll
                for (int j = 0; j < 4; j++) {
                    float x = G[mt][j][h].x, y = G[mt][j][h].y;
                    float qx = x*x, qy = y*y;
                    pg[mt][h] += qx + qy;
                    float cx = qx*x, cy = qy*y;
                    pc[mt][h] = fmaf(cx, cx, pc[mt][h]);
                    pc[mt][h] = fmaf(cy, cy, pc[mt][h]);
                }
        float tt[2][2];
        #pragma unroll
        for (int mt = 0; mt < 2; mt++)
            #pragma unroll
            for (int h = 0; h < 2; h++) {
                float a = pg[mt][h], b = pc[mt][h];
                a += __shfl_xor_sync(0xffffffffu, a, 1);
                a += __shfl_xor_sync(0xffffffffu, a, 2);
                b += __shfl_xor_sync(0xffffffffu, b, 1);
                b += __shfl_xor_sync(0xffffffffu, b, 2);
                tt[mt][h] = PATW * sqrtf(a) / (sqrtf(b) + EPSF);
            }

        // ---- x = g + t*g^3, fp16 2-term split -> A fragments in registers --
        uint32_t Ah[2][2][4], Al[2][2][4];
        #pragma unroll
        for (int mt = 0; mt < 2; mt++)
            #pragma unroll
            for (int ks = 0; ks < 2; ks++)
                #pragma unroll
                for (int half = 0; half < 2; half++)
                    #pragma unroll
                    for (int h = 0; h < 2; h++) {
                        float2 gv = G[mt][2*ks + half][h];
                        float T = tt[mt][h];
                        float x0 = fmaf(T * gv.x * gv.x, gv.x, gv.x);
                        float x1 = fmaf(T * gv.y * gv.y, gv.y, gv.y);
                        uint32_t p = packh2(x0, x1);
                        Ah[mt][ks][half*2 + h] = p;
                        Al[mt][ks][half*2 + h] = packh2(x0 - h2f_lo(p), x1 - h2f_hi(p));
                    }

        // ---- B1 fragments ----
        uint32_t Bf[2][8][2];
        #pragma unroll
        for (int ks = 0; ks < 2; ks++)
            #pragma unroll
            for (int np = 0; np < 4; np++) {
                uint32_t a = b1_b + (uint32_t)(np*16 + ((lane>>4)<<3) + (lane&7)) * (B1STR*2)
                           + (uint32_t)(ks*16)*2 + (((lane>>3)&1) << 4);
                ldm4(&Bf[ks][2*np][0], a);
            }

        // ---- C1 init: b1[n] + pot[m]*W1[32][n] (fp32 exact) ----
        float C[2][8][4];
        const int nb = (lane & 3) * 2;
        float pv[2][2];
        #pragma unroll
        for (int mt = 0; mt < 2; mt++) {
            pv[mt][0] = psm[m0 + mt*16 + (lane >> 2)];
            pv[mt][1] = psm[m0 + mt*16 + (lane >> 2) + 8];
        }
        #pragma unroll
        for (int nt = 0; nt < 8; nt++) {
            int n = nt*8 + nb;
            float bb0 = b1s[n], bb1 = b1s[n+1], w0 = w1p[n], w1v = w1p[n+1];
            #pragma unroll
            for (int mt = 0; mt < 2; mt++) {
                C[mt][nt][0] = fmaf(pv[mt][0], w0,  bb0);
                C[mt][nt][1] = fmaf(pv[mt][0], w1v, bb1);
                C[mt][nt][2] = fmaf(pv[mt][1], w0,  bb0);
                C[mt][nt][3] = fmaf(pv[mt][1], w1v, bb1);
            }
        }

        // ---- GEMM1: xh*w + xl*w ----
        #pragma unroll
        for (int ks = 0; ks < 2; ks++)
            #pragma unroll
            for (int mt = 0; mt < 2; mt++)
                #pragma unroll
                for (int nt = 0; nt < 8; nt++)
                    mma16816(C[mt][nt], Ah[mt][ks], Bf[ks][nt]);
        #pragma unroll
        for (int ks = 0; ks < 2; ks++)
            #pragma unroll
            for (int mt = 0; mt < 2; mt++)
                #pragma unroll
                for (int nt = 0; nt < 8; nt++)
                    mma16816(C[mt][nt], Al[mt][ks], Bf[ks][nt]);

        // ---- relu + fp16 split -> A2 fragments ----
        uint32_t Hh[2][4][4], Hl[2][4][4];
        #pragma unroll
        for (int mt = 0; mt < 2; mt++)
            #pragma unroll
            for (int ks = 0; ks < 4; ks++)
                #pragma unroll
                for (int q = 0; q < 4; q++) {
                    int nt = 2*ks + (q >> 1);
                    float hA = fmaxf(C[mt][nt][(q & 1) * 2],     0.f);
                    float hB = fmaxf(C[mt][nt][(q & 1) * 2 + 1], 0.f);
                    uint32_t p = packh2(hA, hB);
                    Hh[mt][ks][q] = p;
                    Hl[mt][ks][q] = packh2(hA - h2f_lo(p), hB - h2f_hi(p));
                }

        // ---- GEMM2: hh*w2 + hl*w2 ----
        float C2[2][4][4];
        #pragma unroll
        for (int mt = 0; mt < 2; mt++)
            #pragma unroll
            for (int nt = 0; nt < 4; nt++)
                #pragma unroll
                for (int q = 0; q < 4; q++) C2[mt][nt][q] = 0.f;

        uint32_t B2f[4][2];
        #pragma unroll
        for (int ks = 0; ks < 4; ks++) {
            #pragma unroll
            for (int np = 0; np < 2; np++) {
                uint32_t a = b2_b + (uint32_t)(np*16 + ((lane>>4)<<3) + (lane&7)) * (B2STR*2)
                           + (uint32_t)(ks*16)*2 + (((lane>>3)&1) << 4);
                ldm4(&B2f[2*np][0], a);
            }
            #pragma unroll
            for (int mt = 0; mt < 2; mt++)
                #pragma unroll
                for (int nt = 0; nt < 4; nt++) {
                    mma16816(C2[mt][nt], Hh[mt][ks], B2f[nt]);
                    mma16816(C2[mt][nt], Hl[mt][ks], B2f[nt]);
                }
        }

        // ---- epilogue: out = C2 + b2 + alpha*g (g re-read, frag order) ----
        {
            float* outb = out + (size_t)t * 4096;
            #pragma unroll
            for (int mt = 0; mt < 2; mt++) {
                int r0 = m0 + mt*16 + (lane >> 2);
                int r1 = r0 + 8;
                #pragma unroll
                for (int nt = 0; nt < 4; nt++) {
                    int n = nt*8 + nb;
                    uint32_t s0 = gb + (uint32_t)(((mt*4 + nt)*2)*256 + lane*8);
                    float2 ga, gc;
                    asm volatile("ld.shared.v2.f32 {%0,%1}, [%2];"
                                 : "=f"(ga.x), "=f"(ga.y) : "r"(s0));
                    asm volatile("ld.shared.v2.f32 {%0,%1}, [%2];"
                                 : "=f"(gc.x), "=f"(gc.y) : "r"(s0 + 256));
                    float bb0 = b2s[n], bb1 = b2s[n+1];
                    float2 o0, o1;
                    o0.x = fmaf(ALPHAF, ga.x, C2[mt][nt][0] + bb0);
                    o0.y = fmaf(ALPHAF, ga.y, C2[mt][nt][1] + bb1);
                    o1.x = fmaf(ALPHAF, gc.x, C2[mt][nt][2] + bb0);
                    o1.y = fmaf(ALPHAF, gc.y, C2[mt][nt][3] + bb1);
                    *(float2*)(outb + r0*32 + n) = o0;
                    *(float2*)(outb + r1*32 + n) = o1;
                }
            }
        }
        cur ^= 1;
    }
}

extern "C" void kernel_launch(void* const* d_in, const int* in_sizes, int n_in,
                              void* d_out, int out_size) {
    const float* grid = (const float*)d_in[0];
    const float* pot  = (const float*)d_in[1];
    const float* W1   = (const float*)d_in[2];
    const float* b1   = (const float*)d_in[3];
    const float* W2   = (const float*)d_in[4];
    const float* b2   = (const float*)d_in[5];
    float* out = (float*)d_out;

    cudaFuncSetAttribute(be_mma, cudaFuncAttributeMaxDynamicSharedMemorySize, SMEMSZ);
    be_mma<<<GRIDC, 128, SMEMSZ>>>(grid, pot, W1, b1, W2, b2, out);
}

// round 13
// speedup vs baseline: 1.8913x; 1.0229x over previous
#include <cuda_runtime.h>
#include <cstdint>

#define ALPHAF 0.3f
#define EPSF   1e-8f
#define PATW   0.1f

#define GRIDC  760          // 152 SMs x 5 CTAs, persistent
#define NTILES 8192

// ---- dynamic smem layout (bytes) ----
// g buffers in FRAGMENT order: per warp 4096B = 16 slots x 256B.
// slot s = (mt*4 + j)*2 + h holds 8x8 fp32 block rows (m0+mt*16+h*8..+7),
// cols (j*8..j*8+7), entry (r&7, colpair p) at offset (r*4+p)*8 (lane-major).
#define O_G0   0        // g frag buf 0: 4 warps x 4096 = 16384
#define O_G1   16384    // g frag buf 1: 16640 (raw-W staging at init)
#define O_B1   33024    // B1 image: 64 rows x 40 halfs = 5120
#define O_B2   38144    // B2 image: 32 rows x 72 halfs = 4608
#define O_P0   42752    // pot buf 0: 128 f32
#define O_P1   43264    // pot buf 1
#define O_B1S  43776    // b1: 64 f32
#define O_W1P  44032    // W1[32][:]: 64 f32
#define O_B2S  44288    // b2: 32 f32
#define SMEMSZ 44416

#define B1STR 40    // halfs (80B rows, conflict-free)
#define B2STR 72    // halfs (144B rows)

static __device__ __forceinline__ void ldm4(uint32_t* r, uint32_t addr) {
    asm volatile("ldmatrix.sync.aligned.m8n8.x4.shared.b16 {%0,%1,%2,%3}, [%4];"
                 : "=r"(r[0]), "=r"(r[1]), "=r"(r[2]), "=r"(r[3]) : "r"(addr));
}
static __device__ __forceinline__ void mma16816(float* c, const uint32_t* a, const uint32_t* b) {
    asm volatile(
        "mma.sync.aligned.m16n8k16.row.col.f32.f16.f16.f32 "
        "{%0,%1,%2,%3},{%4,%5,%6,%7},{%8,%9},{%0,%1,%2,%3};"
        : "+f"(c[0]), "+f"(c[1]), "+f"(c[2]), "+f"(c[3])
        : "r"(a[0]), "r"(a[1]), "r"(a[2]), "r"(a[3]), "r"(b[0]), "r"(b[1]));
}
static __device__ __forceinline__ uint32_t packh2(float lo, float hi) {
    uint32_t r;
    asm("{\n\t.reg .f16 l, h;\n\t"
        "cvt.rn.f16.f32 l, %1;\n\t"
        "cvt.rn.f16.f32 h, %2;\n\t"
        "mov.b32 %0, {l, h};\n\t}"
        : "=r"(r) : "f"(lo), "f"(hi));
    return r;
}
static __device__ __forceinline__ float h2f_lo(uint32_t p) {
    float f;
    asm("{\n\t.reg .f16 l, h;\n\tmov.b32 {l, h}, %1;\n\tcvt.f32.f16 %0, l;\n\t}"
        : "=f"(f) : "r"(p));
    return f;
}
static __device__ __forceinline__ float h2f_hi(uint32_t p) {
    float f;
    asm("{\n\t.reg .f16 l, h;\n\tmov.b32 {l, h}, %1;\n\tcvt.f32.f16 %0, h;\n\t}"
        : "=f"(f) : "r"(p));
    return f;
}
static __device__ __forceinline__ void cpa16(uint32_t dst, const void* src) {
    asm volatile("cp.async.ca.shared.global [%0], [%1], 16;" :: "r"(dst), "l"(src));
}

__global__ void __launch_bounds__(128, 5)
be_mma(const float* __restrict__ grid, const float* __restrict__ pot,
       const float* __restrict__ W1,   const float* __restrict__ b1,
       const float* __restrict__ W2,   const float* __restrict__ b2,
       float* __restrict__ out)
{
    extern __shared__ __align__(16) unsigned char sm[];
    float* b1s = (float*)(sm + O_B1S);
    float* w1p = (float*)(sm + O_W1P);
    float* b2s = (float*)(sm + O_B2S);
    unsigned short* img1 = (unsigned short*)(sm + O_B1);
    unsigned short* img2 = (unsigned short*)(sm + O_B2);

    const int tid  = threadIdx.x;
    const int lane = tid & 31;
    const int w    = tid >> 5;
    const int m0   = w * 32;

    const uint32_t g0b  = (uint32_t)__cvta_generic_to_shared(sm + O_G0) + w * 4096;
    const uint32_t g1b  = (uint32_t)__cvta_generic_to_shared(sm + O_G1) + w * 4096;
    const uint32_t b1_b = (uint32_t)__cvta_generic_to_shared(sm + O_B1);
    const uint32_t b2_b = (uint32_t)__cvta_generic_to_shared(sm + O_B2);
    const uint32_t p0b  = (uint32_t)__cvta_generic_to_shared(sm + O_P0);
    const uint32_t p1b  = (uint32_t)__cvta_generic_to_shared(sm + O_P1);

    // per-lane constants for the fragment-order cp.async scatter
    const int cc_c  = lane & 7;
    const int cc_j  = cc_c >> 1;
    const int cc_p0 = (cc_c & 1) * 2;
    const int cc_rb = lane >> 3;

    // ===== prologue: prefetch tile-0 warp slice into g buf 0 (frag order) ==
    {
        const float* src = grid + (size_t)blockIdx.x * 4096 + m0 * 32;
        #pragma unroll
        for (int cc = 0; cc < 8; cc++) {
            int f   = lane + 32 * cc;
            int row = cc_rb + 4 * cc;
            int mt = row >> 4, h = (row >> 3) & 1, rr = row & 7;
            uint32_t dst = g0b + (uint32_t)(((mt*4 + cc_j)*2 + h)*256 + (rr*4 + cc_p0)*8);
            cpa16(dst, src + f * 4);
        }
        if (lane < 8)
            cpa16(p0b + (uint32_t)(m0 + lane * 4) * 4,
                  pot + (size_t)blockIdx.x * 128 + m0 + lane * 4);
        asm volatile("cp.async.commit_group;");
    }

    // ===== one-time weight build (raw staging inside g-buf-1 region) =======
    {
        float* rw1 = (float*)(sm + O_G1);          // 2112 f32
        float* rw2 = (float*)(sm + O_G1 + 8448);   // 2048 f32
        #pragma unroll
        for (int i = tid; i < 2112; i += 128) rw1[i] = W1[i];
        #pragma unroll
        for (int i = tid; i < 2048; i += 128) rw2[i] = W2[i];
        if (tid < 64) b1s[tid] = b1[tid];
        if (tid < 32) b2s[tid] = b2[tid];
        __syncthreads();

        if (tid < 64) {                     // W1 column n = tid -> fp16
            const int n = tid;
            uint32_t ph[16];
            #pragma unroll
            for (int kk = 0; kk < 16; kk++)
                ph[kk] = packh2(rw1[(2*kk)*64 + n], rw1[(2*kk+1)*64 + n]);
            uint4* dh = (uint4*)(img1 + n * B1STR);
            #pragma unroll
            for (int q = 0; q < 4; q++)
                dh[q] = make_uint4(ph[4*q], ph[4*q+1], ph[4*q+2], ph[4*q+3]);
            w1p[n] = rw1[32 * 64 + n];
        } else {                            // W2 column n2, K-half kh -> fp16
            const int n2 = (tid - 64) >> 1;
            const int kh = (tid & 1) * 32;
            uint32_t ph[16];
            #pragma unroll
            for (int kk = 0; kk < 16; kk++) {
                int k = kh + 2 * kk;
                ph[kk] = packh2(rw2[k*32 + n2], rw2[(k+1)*32 + n2]);
            }
            uint4* dh = (uint4*)(img2 + n2 * B2STR + kh);
            #pragma unroll
            for (int q = 0; q < 4; q++)
                dh[q] = make_uint4(ph[4*q], ph[4*q+1], ph[4*q+2], ph[4*q+3]);
        }
        __syncthreads();
    }

    // ===== persistent per-warp tile loop ====================================
    const uint32_t gB[2] = { g0b, g1b };
    const uint32_t pB[2] = { p0b, p1b };
    const unsigned char* const pP[2] = { sm + O_P0, sm + O_P1 };

    int cur = 0;
    for (int t = blockIdx.x; t < NTILES; t += GRIDC) {
        // ---- prefetch tile t+GRIDC into buf cur^1 (overlaps whole iter) ----
        {
            int tn = t + GRIDC;
            if (tn < NTILES) {
                const float* src = grid + (size_t)tn * 4096 + m0 * 32;
                uint32_t db = gB[cur ^ 1];
                #pragma unroll
                for (int cc = 0; cc < 8; cc++) {
                    int f   = lane + 32 * cc;
                    int row = cc_rb + 4 * cc;
                    int mt = row >> 4, h = (row >> 3) & 1, rr = row & 7;
                    uint32_t dst = db + (uint32_t)(((mt*4 + cc_j)*2 + h)*256 + (rr*4 + cc_p0)*8);
                    cpa16(dst, src + f * 4);
                }
                if (lane < 8)
                    cpa16(pB[cur ^ 1] + (uint32_t)(m0 + lane * 4) * 4,
                          pot + (size_t)tn * 128 + m0 + lane * 4);
            }
            asm volatile("cp.async.commit_group;");
            asm volatile("cp.async.wait_group 1;");      // tile t's data ready
        }

        const uint32_t gb = gB[cur];
        const float* psm  = (const float*)pP[cur];

        // ---- load g fragments (conflict-free LDS.64) ----
        float2 G[2][4][2];
        #pragma unroll
        for (int mt = 0; mt < 2; mt++)
            #pragma unroll
            for (int j = 0; j < 4; j++)
                #pragma unroll
                for (int h = 0; h < 2; h++) {
                    uint32_t a = gb + (uint32_t)((((mt*4 + j)*2 + h)*256) + lane*8);
                    float2 v;
                    asm volatile("ld.shared.v2.f32 {%0,%1}, [%2];"
                                 : "=f"(v.x), "=f"(v.y) : "r"(a));
                    G[mt][j][h] = v;
                }

        // ---- row norms via quad shfl ----
        float pg[2][2] = {{0.f,0.f},{0.f,0.f}}, pc[2][2] = {{0.f,0.f},{0.f,0.f}};
        #pragma unroll
        for (int mt = 0; mt < 2; mt++)
            #pragma unroll
            for (int h = 0; h < 2; h++)
                #pragma unroll
                for (int j = 0; j < 4; j++) {
                    float x = G[mt][j][h].x, y = G[mt][j][h].y;
                    float qx = x*x, qy = y*y;
                    pg[mt][h] += qx + qy;
                    float cx = qx*x, cy = qy*y;
                    pc[mt][h] = fmaf(cx, cx, pc[mt][h]);
                    pc[mt][h] = fmaf(cy, cy, pc[mt][h]);
                }
        float tt[2][2];
        #pragma unroll
        for (int mt = 0; mt < 2; mt++)
            #pragma unroll
            for (int h = 0; h < 2; h++) {
                float a = pg[mt][h], b = pc[mt][h];
                a += __shfl_xor_sync(0xffffffffu, a, 1);
                a += __shfl_xor_sync(0xffffffffu, a, 2);
                b += __shfl_xor_sync(0xffffffffu, b, 1);
                b += __shfl_xor_sync(0xffffffffu, b, 2);
                tt[mt][h] = PATW * sqrtf(a) / (sqrtf(b) + EPSF);
            }

        // ---- x = g + t*g^3, fp16 2-term split -> A fragments in registers --
        uint32_t Ah[2][2][4], Al[2][2][4];
        #pragma unroll
        for (int mt = 0; mt < 2; mt++)
            #pragma unroll
            for (int ks = 0; ks < 2; ks++)
                #pragma unroll
                for (int half = 0; half < 2; half++)
                    #pragma unroll
                    for (int h = 0; h < 2; h++) {
                        float2 gv = G[mt][2*ks + half][h];
                        float T = tt[mt][h];
                        float x0 = fmaf(T * gv.x * gv.x, gv.x, gv.x);
                        float x1 = fmaf(T * gv.y * gv.y, gv.y, gv.y);
                        uint32_t p = packh2(x0, x1);
                        Ah[mt][ks][half*2 + h] = p;
                        Al[mt][ks][half*2 + h] = packh2(x0 - h2f_lo(p), x1 - h2f_hi(p));
                    }

        // ---- pot values for C1 init ----
        const int nb = (lane & 3) * 2;
        float pv[2][2];
        #pragma unroll
        for (int mt = 0; mt < 2; mt++) {
            pv[mt][0] = psm[m0 + mt*16 + (lane >> 2)];
            pv[mt][1] = psm[m0 + mt*16 + (lane >> 2) + 8];
        }

        // ---- GEMM1 in nt-pair blocks, fused relu+pack -> Hh ----
        uint32_t Hh[2][4][4];
        #pragma unroll
        for (int p = 0; p < 4; p++) {        // nt pair (2p, 2p+1); p == GEMM2 ks
            // B1 fragments for rows 16p..16p+15
            uint32_t Bf[2][2][2];            // [ks][ntin][2]
            #pragma unroll
            for (int ks = 0; ks < 2; ks++) {
                uint32_t a = b1_b + (uint32_t)(p*16 + ((lane>>4)<<3) + (lane&7)) * (B1STR*2)
                           + (uint32_t)(ks*16)*2 + (((lane>>3)&1) << 4);
                ldm4(&Bf[ks][0][0], a);
            }
            // C pair init: b1[n] + pot*W1[32][n]
            float C[2][2][4];
            #pragma unroll
            for (int ntin = 0; ntin < 2; ntin++) {
                int n = (2*p + ntin)*8 + nb;
                float bb0 = b1s[n], bb1 = b1s[n+1], w0 = w1p[n], w1v = w1p[n+1];
                #pragma unroll
                for (int mt = 0; mt < 2; mt++) {
                    C[mt][ntin][0] = fmaf(pv[mt][0], w0,  bb0);
                    C[mt][ntin][1] = fmaf(pv[mt][0], w1v, bb1);
                    C[mt][ntin][2] = fmaf(pv[mt][1], w0,  bb0);
                    C[mt][ntin][3] = fmaf(pv[mt][1], w1v, bb1);
                }
            }
            #pragma unroll
            for (int ks = 0; ks < 2; ks++)
                #pragma unroll
                for (int mt = 0; mt < 2; mt++)
                    #pragma unroll
                    for (int ntin = 0; ntin < 2; ntin++)
                        mma16816(C[mt][ntin], Ah[mt][ks], Bf[ks][ntin]);
            #pragma unroll
            for (int ks = 0; ks < 2; ks++)
                #pragma unroll
                for (int mt = 0; mt < 2; mt++)
                    #pragma unroll
                    for (int ntin = 0; ntin < 2; ntin++)
                        mma16816(C[mt][ntin], Al[mt][ks], Bf[ks][ntin]);
            // relu + single-term fp16 pack
            #pragma unroll
            for (int mt = 0; mt < 2; mt++)
                #pragma unroll
                for (int q = 0; q < 4; q++) {
                    int ntin = q >> 1;
                    float hA = fmaxf(C[mt][ntin][(q & 1) * 2],     0.f);
                    float hB = fmaxf(C[mt][ntin][(q & 1) * 2 + 1], 0.f);
                    Hh[mt][p][q] = packh2(hA, hB);
                }
        }

        // ---- GEMM2: single-term h * w2 ----
        float C2[2][4][4];
        #pragma unroll
        for (int mt = 0; mt < 2; mt++)
            #pragma unroll
            for (int nt = 0; nt < 4; nt++)
                #pragma unroll
                for (int q = 0; q < 4; q++) C2[mt][nt][q] = 0.f;

        uint32_t B2f[4][2];
        #pragma unroll
        for (int ks = 0; ks < 4; ks++) {
            #pragma unroll
            for (int np = 0; np < 2; np++) {
                uint32_t a = b2_b + (uint32_t)(np*16 + ((lane>>4)<<3) + (lane&7)) * (B2STR*2)
                           + (uint32_t)(ks*16)*2 + (((lane>>3)&1) << 4);
                ldm4(&B2f[2*np][0], a);
            }
            #pragma unroll
            for (int mt = 0; mt < 2; mt++)
                #pragma unroll
                for (int nt = 0; nt < 4; nt++)
                    mma16816(C2[mt][nt], Hh[mt][ks], B2f[nt]);
        }

        // ---- epilogue: out = C2 + b2 + alpha*g (g re-read, frag order) ----
        {
            float* outb = out + (size_t)t * 4096;
            #pragma unroll
            for (int mt = 0; mt < 2; mt++) {
                int r0 = m0 + mt*16 + (lane >> 2);
                int r1 = r0 + 8;
                #pragma unroll
                for (int nt = 0; nt < 4; nt++) {
                    int n = nt*8 + nb;
                    uint32_t s0 = gb + (uint32_t)(((mt*4 + nt)*2)*256 + lane*8);
                    float2 ga, gc;
                    asm volatile("ld.shared.v2.f32 {%0,%1}, [%2];"
                                 : "=f"(ga.x), "=f"(ga.y) : "r"(s0));
                    asm volatile("ld.shared.v2.f32 {%0,%1}, [%2];"
                                 : "=f"(gc.x), "=f"(gc.y) : "r"(s0 + 256));
                    float bb0 = b2s[n], bb1 = b2s[n+1];
                    float2 o0, o1;
                    o0.x = fmaf(ALPHAF, ga.x, C2[mt][nt][0] + bb0);
                    o0.y = fmaf(ALPHAF, ga.y, C2[mt][nt][1] + bb1);
                    o1.x = fmaf(ALPHAF, gc.x, C2[mt][nt][2] + bb0);
                    o1.y = fmaf(ALPHAF, gc.y, C2[mt][nt][3] + bb1);
                    *(float2*)(outb + r0*32 + n) = o0;
                    *(float2*)(outb + r1*32 + n) = o1;
                }
            }
        }
        cur ^= 1;
    }
}

extern "C" void kernel_launch(void* const* d_in, const int* in_sizes, int n_in,
                              void* d_out, int out_size) {
    const float* grid = (const float*)d_in[0];
    const float* pot  = (const float*)d_in[1];
    const float* W1   = (const float*)d_in[2];
    const float* b1   = (const float*)d_in[3];
    const float* W2   = (const float*)d_in[4];
    const float* b2   = (const float*)d_in[5];
    float* out = (float*)d_out;

    cudaFuncSetAttribute(be_mma, cudaFuncAttributeMaxDynamicSharedMemorySize, SMEMSZ);
    be_mma<<<GRIDC, 128, SMEMSZ>>>(grid, pot, W1, b1, W2, b2, out);
}

// round 14
// speedup vs baseline: 2.0025x; 1.0588x over previous
#include <cuda_runtime.h>
#include <cstdint>

#define ALPHAF 0.3f
#define EPSF   1e-8f
#define PATW   0.1f

#define GRIDC  760          // 152 SMs x 5 CTAs, persistent
#define NTILES 8192

// ---- dynamic smem layout (bytes) ----
// g buffers in FRAGMENT order: per warp 4096B = 16 slots x 256B.
// slot s = (mt*4 + j)*2 + h holds 8x8 fp32 block rows (m0+mt*16+h*8..+7),
// cols (j*8..j*8+7), entry (r&7, colpair p) at offset (r*4+p)*8 (lane-major).
#define O_G0   0        // g frag buf 0: 4 warps x 4096 = 16384
#define O_G1   16384    // g frag buf 1: 16640 (raw-W staging at init)
#define O_B1   33024    // B1 image: 64 rows x 40 halfs = 5120
#define O_B2   38144    // B2 image: 32 rows x 72 halfs = 4608
#define O_P0   42752    // pot buf 0: 128 f32
#define O_P1   43264    // pot buf 1
#define O_B1S  43776    // b1: 64 f32
#define O_W1P  44032    // W1[32][:]: 64 f32
#define O_B2S  44288    // b2: 32 f32
#define SMEMSZ 44416

#define B1STR 40    // halfs (80B rows, conflict-free)
#define B2STR 72    // halfs (144B rows)

static __device__ __forceinline__ void ldm4(uint32_t* r, uint32_t addr) {
    asm volatile("ldmatrix.sync.aligned.m8n8.x4.shared.b16 {%0,%1,%2,%3}, [%4];"
                 : "=r"(r[0]), "=r"(r[1]), "=r"(r[2]), "=r"(r[3]) : "r"(addr));
}
static __device__ __forceinline__ void mma16816(float* c, const uint32_t* a, const uint32_t* b) {
    asm volatile(
        "mma.sync.aligned.m16n8k16.row.col.f32.f16.f16.f32 "
        "{%0,%1,%2,%3},{%4,%5,%6,%7},{%8,%9},{%0,%1,%2,%3};"
        : "+f"(c[0]), "+f"(c[1]), "+f"(c[2]), "+f"(c[3])
        : "r"(a[0]), "r"(a[1]), "r"(a[2]), "r"(a[3]), "r"(b[0]), "r"(b[1]));
}
static __device__ __forceinline__ uint32_t packh2(float lo, float hi) {
    uint32_t r;
    asm("{\n\t.reg .f16 l, h;\n\t"
        "cvt.rn.f16.f32 l, %1;\n\t"
        "cvt.rn.f16.f32 h, %2;\n\t"
        "mov.b32 %0, {l, h};\n\t}"
        : "=r"(r) : "f"(lo), "f"(hi));
    return r;
}
static __device__ __forceinline__ void cpa16(uint32_t dst, const void* src) {
    asm volatile("cp.async.ca.shared.global [%0], [%1], 16;" :: "r"(dst), "l"(src));
}

__global__ void __launch_bounds__(128, 5)
be_mma(const float* __restrict__ grid, const float* __restrict__ pot,
       const float* __restrict__ W1,   const float* __restrict__ b1,
       const float* __restrict__ W2,   const float* __restrict__ b2,
       float* __restrict__ out)
{
    extern __shared__ __align__(16) unsigned char sm[];
    float* b1s = (float*)(sm + O_B1S);
    float* w1p = (float*)(sm + O_W1P);
    float* b2s = (float*)(sm + O_B2S);
    unsigned short* img1 = (unsigned short*)(sm + O_B1);
    unsigned short* img2 = (unsigned short*)(sm + O_B2);

    const int tid  = threadIdx.x;
    const int lane = tid & 31;
    const int w    = tid >> 5;
    const int m0   = w * 32;

    const uint32_t g0b  = (uint32_t)__cvta_generic_to_shared(sm + O_G0) + w * 4096;
    const uint32_t g1b  = (uint32_t)__cvta_generic_to_shared(sm + O_G1) + w * 4096;
    const uint32_t b1_b = (uint32_t)__cvta_generic_to_shared(sm + O_B1);
    const uint32_t b2_b = (uint32_t)__cvta_generic_to_shared(sm + O_B2);
    const uint32_t p0b  = (uint32_t)__cvta_generic_to_shared(sm + O_P0);
    const uint32_t p1b  = (uint32_t)__cvta_generic_to_shared(sm + O_P1);

    // per-lane constants for the fragment-order cp.async scatter
    const int cc_c  = lane & 7;
    const int cc_j  = cc_c >> 1;
    const int cc_p0 = (cc_c & 1) * 2;
    const int cc_rb = lane >> 3;

    // ===== prologue: prefetch tile-0 warp slice into g buf 0 (frag order) ==
    {
        const float* src = grid + (size_t)blockIdx.x * 4096 + m0 * 32;
        #pragma unroll
        for (int cc = 0; cc < 8; cc++) {
            int f   = lane + 32 * cc;
            int row = cc_rb + 4 * cc;
            int mt = row >> 4, h = (row >> 3) & 1, rr = row & 7;
            uint32_t dst = g0b + (uint32_t)(((mt*4 + cc_j)*2 + h)*256 + (rr*4 + cc_p0)*8);
            cpa16(dst, src + f * 4);
        }
        if (lane < 8)
            cpa16(p0b + (uint32_t)(m0 + lane * 4) * 4,
                  pot + (size_t)blockIdx.x * 128 + m0 + lane * 4);
        asm volatile("cp.async.commit_group;");
    }

    // ===== one-time weight build (raw staging inside g-buf-1 region) =======
    {
        float* rw1 = (float*)(sm + O_G1);          // 2112 f32
        float* rw2 = (float*)(sm + O_G1 + 8448);   // 2048 f32
        #pragma unroll
        for (int i = tid; i < 2112; i += 128) rw1[i] = W1[i];
        #pragma unroll
        for (int i = tid; i < 2048; i += 128) rw2[i] = W2[i];
        if (tid < 64) b1s[tid] = b1[tid];
        if (tid < 32) b2s[tid] = b2[tid];
        __syncthreads();

        if (tid < 64) {                     // W1 column n = tid -> fp16
            const int n = tid;
            uint32_t ph[16];
            #pragma unroll
            for (int kk = 0; kk < 16; kk++)
                ph[kk] = packh2(rw1[(2*kk)*64 + n], rw1[(2*kk+1)*64 + n]);
            uint4* dh = (uint4*)(img1 + n * B1STR);
            #pragma unroll
            for (int q = 0; q < 4; q++)
                dh[q] = make_uint4(ph[4*q], ph[4*q+1], ph[4*q+2], ph[4*q+3]);
            w1p[n] = rw1[32 * 64 + n];
        } else {                            // W2 column n2, K-half kh -> fp16
            const int n2 = (tid - 64) >> 1;
            const int kh = (tid & 1) * 32;
            uint32_t ph[16];
            #pragma unroll
            for (int kk = 0; kk < 16; kk++) {
                int k = kh + 2 * kk;
                ph[kk] = packh2(rw2[k*32 + n2], rw2[(k+1)*32 + n2]);
            }
            uint4* dh = (uint4*)(img2 + n2 * B2STR + kh);
            #pragma unroll
            for (int q = 0; q < 4; q++)
                dh[q] = make_uint4(ph[4*q], ph[4*q+1], ph[4*q+2], ph[4*q+3]);
        }
        __syncthreads();
    }

    // ===== persistent per-warp tile loop ====================================
    const uint32_t gB[2] = { g0b, g1b };
    const uint32_t pB[2] = { p0b, p1b };
    const unsigned char* const pP[2] = { sm + O_P0, sm + O_P1 };

    int cur = 0;
    for (int t = blockIdx.x; t < NTILES; t += GRIDC) {
        // ---- prefetch tile t+GRIDC into buf cur^1 (overlaps whole iter) ----
        {
            int tn = t + GRIDC;
            if (tn < NTILES) {
                const float* src = grid + (size_t)tn * 4096 + m0 * 32;
                uint32_t db = gB[cur ^ 1];
                #pragma unroll
                for (int cc = 0; cc < 8; cc++) {
                    int f   = lane + 32 * cc;
                    int row = cc_rb + 4 * cc;
                    int mt = row >> 4, h = (row >> 3) & 1, rr = row & 7;
                    uint32_t dst = db + (uint32_t)(((mt*4 + cc_j)*2 + h)*256 + (rr*4 + cc_p0)*8);
                    cpa16(dst, src + f * 4);
                }
                if (lane < 8)
                    cpa16(pB[cur ^ 1] + (uint32_t)(m0 + lane * 4) * 4,
                          pot + (size_t)tn * 128 + m0 + lane * 4);
            }
            asm volatile("cp.async.commit_group;");
            asm volatile("cp.async.wait_group 1;");      // tile t's data ready
        }

        const uint32_t gb = gB[cur];
        const float* psm  = (const float*)pP[cur];

        // ---- load g fragments (conflict-free LDS.64) ----
        float2 G[2][4][2];
        #pragma unroll
        for (int mt = 0; mt < 2; mt++)
            #pragma unroll
            for (int j = 0; j < 4; j++)
                #pragma unroll
                for (int h = 0; h < 2; h++) {
                    uint32_t a = gb + (uint32_t)((((mt*4 + j)*2 + h)*256) + lane*8);
                    float2 v;
                    asm volatile("ld.shared.v2.f32 {%0,%1}, [%2];"
                                 : "=f"(v.x), "=f"(v.y) : "r"(a));
                    G[mt][j][h] = v;
                }

        // ---- row norms via quad shfl ----
        float pg[2][2] = {{0.f,0.f},{0.f,0.f}}, pc[2][2] = {{0.f,0.f},{0.f,0.f}};
        #pragma unroll
        for (int mt = 0; mt < 2; mt++)
            #pragma unroll
            for (int h = 0; h < 2; h++)
                #pragma unroll
                for (int j = 0; j < 4; j++) {
                    float x = G[mt][j][h].x, y = G[mt][j][h].y;
                    float qx = x*x, qy = y*y;
                    pg[mt][h] += qx + qy;
                    float cx = qx*x, cy = qy*y;
                    pc[mt][h] = fmaf(cx, cx, pc[mt][h]);
                    pc[mt][h] = fmaf(cy, cy, pc[mt][h]);
                }
        float tt[2][2];
        #pragma unroll
        for (int mt = 0; mt < 2; mt++)
            #pragma unroll
            for (int h = 0; h < 2; h++) {
                float a = pg[mt][h], b = pc[mt][h];
                a += __shfl_xor_sync(0xffffffffu, a, 1);
                a += __shfl_xor_sync(0xffffffffu, a, 2);
                b += __shfl_xor_sync(0xffffffffu, b, 1);
                b += __shfl_xor_sync(0xffffffffu, b, 2);
                tt[mt][h] = PATW * sqrtf(a) / (sqrtf(b) + EPSF);
            }

        // ---- x = g + t*g^3, single fp16 -> A fragments in registers ----
        uint32_t Ah[2][2][4];
        #pragma unroll
        for (int mt = 0; mt < 2; mt++)
            #pragma unroll
            for (int ks = 0; ks < 2; ks++)
                #pragma unroll
                for (int half = 0; half < 2; half++)
                    #pragma unroll
                    for (int h = 0; h < 2; h++) {
                        float2 gv = G[mt][2*ks + half][h];
                        float T = tt[mt][h];
                        float x0 = fmaf(T * gv.x * gv.x, gv.x, gv.x);
                        float x1 = fmaf(T * gv.y * gv.y, gv.y, gv.y);
                        Ah[mt][ks][half*2 + h] = packh2(x0, x1);
                    }

        // ---- pot values for C1 init ----
        const int nb = (lane & 3) * 2;
        float pv[2][2];
        #pragma unroll
        for (int mt = 0; mt < 2; mt++) {
            pv[mt][0] = psm[m0 + mt*16 + (lane >> 2)];
            pv[mt][1] = psm[m0 + mt*16 + (lane >> 2) + 8];
        }

        // ---- GEMM1 in nt-pair blocks, fused relu+pack -> Hh ----
        uint32_t Hh[2][4][4];
        #pragma unroll
        for (int p = 0; p < 4; p++) {        // nt pair (2p, 2p+1); p == GEMM2 ks
            uint32_t Bf[2][2][2];            // [ks][ntin][2]
            #pragma unroll
            for (int ks = 0; ks < 2; ks++) {
                uint32_t a = b1_b + (uint32_t)(p*16 + ((lane>>4)<<3) + (lane&7)) * (B1STR*2)
                           + (uint32_t)(ks*16)*2 + (((lane>>3)&1) << 4);
                ldm4(&Bf[ks][0][0], a);
            }
            float C[2][2][4];
            #pragma unroll
            for (int ntin = 0; ntin < 2; ntin++) {
                int n = (2*p + ntin)*8 + nb;
                float bb0 = b1s[n], bb1 = b1s[n+1], w0 = w1p[n], w1v = w1p[n+1];
                #pragma unroll
                for (int mt = 0; mt < 2; mt++) {
                    C[mt][ntin][0] = fmaf(pv[mt][0], w0,  bb0);
                    C[mt][ntin][1] = fmaf(pv[mt][0], w1v, bb1);
                    C[mt][ntin][2] = fmaf(pv[mt][1], w0,  bb0);
                    C[mt][ntin][3] = fmaf(pv[mt][1], w1v, bb1);
                }
            }
            #pragma unroll
            for (int ks = 0; ks < 2; ks++)
                #pragma unroll
                for (int mt = 0; mt < 2; mt++)
                    #pragma unroll
                    for (int ntin = 0; ntin < 2; ntin++)
                        mma16816(C[mt][ntin], Ah[mt][ks], Bf[ks][ntin]);
            #pragma unroll
            for (int mt = 0; mt < 2; mt++)
                #pragma unroll
                for (int q = 0; q < 4; q++) {
                    int ntin = q >> 1;
                    float hA = fmaxf(C[mt][ntin][(q & 1) * 2],     0.f);
                    float hB = fmaxf(C[mt][ntin][(q & 1) * 2 + 1], 0.f);
                    Hh[mt][p][q] = packh2(hA, hB);
                }
        }

        // ---- GEMM2: single-term h * w2 ----
        float C2[2][4][4];
        #pragma unroll
        for (int mt = 0; mt < 2; mt++)
            #pragma unroll
            for (int nt = 0; nt < 4; nt++)
                #pragma unroll
                for (int q = 0; q < 4; q++) C2[mt][nt][q] = 0.f;

        uint32_t B2f[4][2];
        #pragma unroll
        for (int ks = 0; ks < 4; ks++) {
            #pragma unroll
            for (int np = 0; np < 2; np++) {
                uint32_t a = b2_b + (uint32_t)(np*16 + ((lane>>4)<<3) + (lane&7)) * (B2STR*2)
                           + (uint32_t)(ks*16)*2 + (((lane>>3)&1) << 4);
                ldm4(&B2f[2*np][0], a);
            }
            #pragma unroll
            for (int mt = 0; mt < 2; mt++)
                #pragma unroll
                for (int nt = 0; nt < 4; nt++)
                    mma16816(C2[mt][nt], Hh[mt][ks], B2f[nt]);
        }

        // ---- epilogue: out = C2 + b2 + alpha*g (g re-read, frag order) ----
        {
            float* outb = out + (size_t)t * 4096;
            #pragma unroll
            for (int mt = 0; mt < 2; mt++) {
                int r0 = m0 + mt*16 + (lane >> 2);
                int r1 = r0 + 8;
                #pragma unroll
                for (int nt = 0; nt < 4; nt++) {
                    int n = nt*8 + nb;
                    uint32_t s0 = gb + (uint32_t)(((mt*4 + nt)*2)*256 + lane*8);
                    float2 ga, gc;
                    asm volatile("ld.shared.v2.f32 {%0,%1}, [%2];"
                                 : "=f"(ga.x), "=f"(ga.y) : "r"(s0));
                    asm volatile("ld.shared.v2.f32 {%0,%1}, [%2];"
                                 : "=f"(gc.x), "=f"(gc.y) : "r"(s0 + 256));
                    float bb0 = b2s[n], bb1 = b2s[n+1];
                    float2 o0, o1;
                    o0.x = fmaf(ALPHAF, ga.x, C2[mt][nt][0] + bb0);
                    o0.y = fmaf(ALPHAF, ga.y, C2[mt][nt][1] + bb1);
                    o1.x = fmaf(ALPHAF, gc.x, C2[mt][nt][2] + bb0);
                    o1.y = fmaf(ALPHAF, gc.y, C2[mt][nt][3] + bb1);
                    *(float2*)(outb + r0*32 + n) = o0;
                    *(float2*)(outb + r1*32 + n) = o1;
                }
            }
        }
        cur ^= 1;
    }
}

extern "C" void kernel_launch(void* const* d_in, const int* in_sizes, int n_in,
                              void* d_out, int out_size) {
    const float* grid = (const float*)d_in[0];
    const float* pot  = (const float*)d_in[1];
    const float* W1   = (const float*)d_in[2];
    const float* b1   = (const float*)d_in[3];
    const float* W2   = (const float*)d_in[4];
    const float* b2   = (const float*)d_in[5];
    float* out = (float*)d_out;

    cudaFuncSetAttribute(be_mma, cudaFuncAttributeMaxDynamicSharedMemorySize, SMEMSZ);
    be_mma<<<GRIDC, 128, SMEMSZ>>>(grid, pot, W1, b1, W2, b2, out);
}

// round 15
// speedup vs baseline: 2.0937x; 1.0456x over previous
#include <cuda_runtime.h>
#include <cstdint>

#define ALPHAF 0.3f
#define PATW   0.1f

#define GRIDC  760          // 152 SMs x 5 CTAs, persistent
#define NTILES 8192

// ---- dynamic smem layout (bytes) ----
// g buffers in FRAGMENT order: per warp 4096B = 16 slots x 256B.
// slot s = (mt*4 + j)*2 + h holds 8x8 fp32 block rows (m0+mt*16+h*8..+7),
// cols (j*8..j*8+7), entry (r&7, colpair p) at offset (r*4+p)*8 (lane-major).
#define O_G0   0        // g frag buf 0: 4 warps x 4096 = 16384
#define O_G1   16384    // g frag buf 1: 16640 (raw-W staging at init)
#define O_B1   33024    // B1 image: 64 rows x 40 halfs = 5120
#define O_B2   38144    // B2 image: 32 rows x 72 halfs = 4608
#define O_P0   42752    // pot buf 0: 128 f32
#define O_P1   43264    // pot buf 1
#define O_B1S  43776    // b1: 64 f32
#define O_W1P  44032    // W1[32][:]: 64 f32
#define O_B2S  44288    // b2: 32 f32
#define SMEMSZ 44416

#define B1STR 40    // halfs (80B rows, conflict-free)
#define B2STR 72    // halfs (144B rows)

static __device__ __forceinline__ void ldm4(uint32_t* r, uint32_t addr) {
    asm volatile("ldmatrix.sync.aligned.m8n8.x4.shared.b16 {%0,%1,%2,%3}, [%4];"
                 : "=r"(r[0]), "=r"(r[1]), "=r"(r[2]), "=r"(r[3]) : "r"(addr));
}
static __device__ __forceinline__ void mma16816(float* c, const uint32_t* a, const uint32_t* b) {
    asm volatile(
        "mma.sync.aligned.m16n8k16.row.col.f32.f16.f16.f32 "
        "{%0,%1,%2,%3},{%4,%5,%6,%7},{%8,%9},{%0,%1,%2,%3};"
        : "+f"(c[0]), "+f"(c[1]), "+f"(c[2]), "+f"(c[3])
        : "r"(a[0]), "r"(a[1]), "r"(a[2]), "r"(a[3]), "r"(b[0]), "r"(b[1]));
}
static __device__ __forceinline__ uint32_t packh2(float lo, float hi) {
    uint32_t r;
    asm("{\n\t.reg .f16 l, h;\n\t"
        "cvt.rn.f16.f32 l, %1;\n\t"
        "cvt.rn.f16.f32 h, %2;\n\t"
        "mov.b32 %0, {l, h};\n\t}"
        : "=r"(r) : "f"(lo), "f"(hi));
    return r;
}
static __device__ __forceinline__ void cpa16(uint32_t dst, const void* src) {
    asm volatile("cp.async.ca.shared.global [%0], [%1], 16;" :: "r"(dst), "l"(src));
}

__global__ void __launch_bounds__(128, 5)
be_mma(const float* __restrict__ grid, const float* __restrict__ pot,
       const float* __restrict__ W1,   const float* __restrict__ b1,
       const float* __restrict__ W2,   const float* __restrict__ b2,
       float* __restrict__ out)
{
    extern __shared__ __align__(16) unsigned char sm[];
    float* b1s = (float*)(sm + O_B1S);
    float* w1p = (float*)(sm + O_W1P);
    float* b2s = (float*)(sm + O_B2S);
    unsigned short* img1 = (unsigned short*)(sm + O_B1);
    unsigned short* img2 = (unsigned short*)(sm + O_B2);

    const int tid  = threadIdx.x;
    const int lane = tid & 31;
    const int w    = tid >> 5;
    const int m0   = w * 32;

    const uint32_t g0b  = (uint32_t)__cvta_generic_to_shared(sm + O_G0) + w * 4096;
    const uint32_t g1b  = (uint32_t)__cvta_generic_to_shared(sm + O_G1) + w * 4096;
    const uint32_t b1_b = (uint32_t)__cvta_generic_to_shared(sm + O_B1);
    const uint32_t b2_b = (uint32_t)__cvta_generic_to_shared(sm + O_B2);
    const uint32_t p0b  = (uint32_t)__cvta_generic_to_shared(sm + O_P0);
    const uint32_t p1b  = (uint32_t)__cvta_generic_to_shared(sm + O_P1);

    // per-lane constants for the fragment-order cp.async scatter
    const int cc_c  = lane & 7;
    const int cc_j  = cc_c >> 1;
    const int cc_p0 = (cc_c & 1) * 2;
    const int cc_rb = lane >> 3;

    // ===== prologue: prefetch tile-0 warp slice into g buf 0 (frag order) ==
    {
        const float* src = grid + (size_t)blockIdx.x * 4096 + m0 * 32;
        #pragma unroll
        for (int cc = 0; cc < 8; cc++) {
            int f   = lane + 32 * cc;
            int row = cc_rb + 4 * cc;
            int mt = row >> 4, h = (row >> 3) & 1, rr = row & 7;
            uint32_t dst = g0b + (uint32_t)(((mt*4 + cc_j)*2 + h)*256 + (rr*4 + cc_p0)*8);
            cpa16(dst, src + f * 4);
        }
        if (lane < 8)
            cpa16(p0b + (uint32_t)(m0 + lane * 4) * 4,
                  pot + (size_t)blockIdx.x * 128 + m0 + lane * 4);
        asm volatile("cp.async.commit_group;");
    }

    // ===== one-time weight build (raw staging inside g-buf-1 region) =======
    {
        float* rw1 = (float*)(sm + O_G1);          // 2112 f32
        float* rw2 = (float*)(sm + O_G1 + 8448);   // 2048 f32
        #pragma unroll
        for (int i = tid; i < 2112; i += 128) rw1[i] = W1[i];
        #pragma unroll
        for (int i = tid; i < 2048; i += 128) rw2[i] = W2[i];
        if (tid < 64) b1s[tid] = b1[tid];
        if (tid < 32) b2s[tid] = b2[tid];
        __syncthreads();

        if (tid < 64) {                     // W1 column n = tid -> fp16
            const int n = tid;
            uint32_t ph[16];
            #pragma unroll
            for (int kk = 0; kk < 16; kk++)
                ph[kk] = packh2(rw1[(2*kk)*64 + n], rw1[(2*kk+1)*64 + n]);
            uint4* dh = (uint4*)(img1 + n * B1STR);
            #pragma unroll
            for (int q = 0; q < 4; q++)
                dh[q] = make_uint4(ph[4*q], ph[4*q+1], ph[4*q+2], ph[4*q+3]);
            w1p[n] = rw1[32 * 64 + n];
        } else {                            // W2 column n2, K-half kh -> fp16
            const int n2 = (tid - 64) >> 1;
            const int kh = (tid & 1) * 32;
            uint32_t ph[16];
            #pragma unroll
            for (int kk = 0; kk < 16; kk++) {
                int k = kh + 2 * kk;
                ph[kk] = packh2(rw2[k*32 + n2], rw2[(k+1)*32 + n2]);
            }
            uint4* dh = (uint4*)(img2 + n2 * B2STR + kh);
            #pragma unroll
            for (int q = 0; q < 4; q++)
                dh[q] = make_uint4(ph[4*q], ph[4*q+1], ph[4*q+2], ph[4*q+3]);
        }
        __syncthreads();
    }

    // ===== persistent per-warp tile loop ====================================
    const uint32_t gB[2] = { g0b, g1b };
    const uint32_t pB[2] = { p0b, p1b };
    const unsigned char* const pP[2] = { sm + O_P0, sm + O_P1 };

    int cur = 0;
    for (int t = blockIdx.x; t < NTILES; t += GRIDC) {
        // ---- prefetch tile t+GRIDC into buf cur^1 (overlaps whole iter) ----
        {
            int tn = t + GRIDC;
            if (tn < NTILES) {
                const float* src = grid + (size_t)tn * 4096 + m0 * 32;
                uint32_t db = gB[cur ^ 1];
                #pragma unroll
                for (int cc = 0; cc < 8; cc++) {
                    int f   = lane + 32 * cc;
                    int row = cc_rb + 4 * cc;
                    int mt = row >> 4, h = (row >> 3) & 1, rr = row & 7;
                    uint32_t dst = db + (uint32_t)(((mt*4 + cc_j)*2 + h)*256 + (rr*4 + cc_p0)*8);
                    cpa16(dst, src + f * 4);
                }
                if (lane < 8)
                    cpa16(pB[cur ^ 1] + (uint32_t)(m0 + lane * 4) * 4,
                          pot + (size_t)tn * 128 + m0 + lane * 4);
            }
            asm volatile("cp.async.commit_group;");
            asm volatile("cp.async.wait_group 1;");      // tile t's data ready
        }

        const uint32_t gb = gB[cur];
        const float* psm  = (const float*)pP[cur];
        const int nb = (lane & 3) * 2;

        // ---- load g fragments (conflict-free LDS.64) ----
        float2 G[2][4][2];
        #pragma unroll
        for (int mt = 0; mt < 2; mt++)
            #pragma unroll
            for (int j = 0; j < 4; j++)
                #pragma unroll
                for (int h = 0; h < 2; h++) {
                    uint32_t a = gb + (uint32_t)((((mt*4 + j)*2 + h)*256) + lane*8);
                    float2 v;
                    asm volatile("ld.shared.v2.f32 {%0,%1}, [%2];"
                                 : "=f"(v.x), "=f"(v.y) : "r"(a));
                    G[mt][j][h] = v;
                }

        // ---- C2 pre-init: b2[n] + alpha*g (epilogue pre-folded; MMA accums on top)
        float C2[2][4][4];
        #pragma unroll
        for (int mt = 0; mt < 2; mt++)
            #pragma unroll
            for (int nt = 0; nt < 4; nt++) {
                int n = nt*8 + nb;
                float bb0 = b2s[n], bb1 = b2s[n+1];
                C2[mt][nt][0] = fmaf(ALPHAF, G[mt][nt][0].x, bb0);
                C2[mt][nt][1] = fmaf(ALPHAF, G[mt][nt][0].y, bb1);
                C2[mt][nt][2] = fmaf(ALPHAF, G[mt][nt][1].x, bb0);
                C2[mt][nt][3] = fmaf(ALPHAF, G[mt][nt][1].y, bb1);
            }

        // ---- row norms via quad shfl ----
        float pg[2][2] = {{0.f,0.f},{0.f,0.f}}, pc[2][2] = {{0.f,0.f},{0.f,0.f}};
        #pragma unroll
        for (int mt = 0; mt < 2; mt++)
            #pragma unroll
            for (int h = 0; h < 2; h++)
                #pragma unroll
                for (int j = 0; j < 4; j++) {
                    float x = G[mt][j][h].x, y = G[mt][j][h].y;
                    float qx = x*x, qy = y*y;
                    pg[mt][h] += qx + qy;
                    float cx = qx*x, cy = qy*y;
                    pc[mt][h] = fmaf(cx, cx, pc[mt][h]);
                    pc[mt][h] = fmaf(cy, cy, pc[mt][h]);
                }
        float tt[2][2];
        #pragma unroll
        for (int mt = 0; mt < 2; mt++)
            #pragma unroll
            for (int h = 0; h < 2; h++) {
                float a = pg[mt][h], b = pc[mt][h];
                a += __shfl_xor_sync(0xffffffffu, a, 1);
                a += __shfl_xor_sync(0xffffffffu, a, 2);
                b += __shfl_xor_sync(0xffffffffu, b, 1);
                b += __shfl_xor_sync(0xffffffffu, b, 2);
                // eps=1e-8 vs sqrt(b)=O(10): relative perturbation ~1e-9, negligible
                tt[mt][h] = PATW * sqrtf(a) * rsqrtf(b);
            }

        // ---- x = g + t*g^3, single fp16 -> A fragments in registers ----
        uint32_t Ah[2][2][4];
        #pragma unroll
        for (int mt = 0; mt < 2; mt++)
            #pragma unroll
            for (int ks = 0; ks < 2; ks++)
                #pragma unroll
                for (int half = 0; half < 2; half++)
                    #pragma unroll
                    for (int h = 0; h < 2; h++) {
                        float2 gv = G[mt][2*ks + half][h];
                        float T = tt[mt][h];
                        float x0 = fmaf(T * gv.x * gv.x, gv.x, gv.x);
                        float x1 = fmaf(T * gv.y * gv.y, gv.y, gv.y);
                        Ah[mt][ks][half*2 + h] = packh2(x0, x1);
                    }

        // ---- pot values for C1 init ----
        float pv[2][2];
        #pragma unroll
        for (int mt = 0; mt < 2; mt++) {
            pv[mt][0] = psm[m0 + mt*16 + (lane >> 2)];
            pv[mt][1] = psm[m0 + mt*16 + (lane >> 2) + 8];
        }

        // ---- fused GEMM1+GEMM2 over nt-pair blocks p (p == GEMM2 ks) ----
        #pragma unroll
        for (int p = 0; p < 4; p++) {
            // B2 fragments for ks=p (issued early; latency hides under GEMM1)
            uint32_t B2f[4][2];
            #pragma unroll
            for (int np = 0; np < 2; np++) {
                uint32_t a = b2_b + (uint32_t)(np*16 + ((lane>>4)<<3) + (lane&7)) * (B2STR*2)
                           + (uint32_t)(p*16)*2 + (((lane>>3)&1) << 4);
                ldm4(&B2f[2*np][0], a);
            }
            // B1 fragments for rows 16p..16p+15
            uint32_t Bf[2][2][2];
            #pragma unroll
            for (int ks = 0; ks < 2; ks++) {
                uint32_t a = b1_b + (uint32_t)(p*16 + ((lane>>4)<<3) + (lane&7)) * (B1STR*2)
                           + (uint32_t)(ks*16)*2 + (((lane>>3)&1) << 4);
                ldm4(&Bf[ks][0][0], a);
            }
            // C pair init: b1[n] + pot*W1[32][n]
            float C[2][2][4];
            #pragma unroll
            for (int ntin = 0; ntin < 2; ntin++) {
                int n = (2*p + ntin)*8 + nb;
                float bb0 = b1s[n], bb1 = b1s[n+1], w0 = w1p[n], w1v = w1p[n+1];
                #pragma unroll
                for (int mt = 0; mt < 2; mt++) {
                    C[mt][ntin][0] = fmaf(pv[mt][0], w0,  bb0);
                    C[mt][ntin][1] = fmaf(pv[mt][0], w1v, bb1);
                    C[mt][ntin][2] = fmaf(pv[mt][1], w0,  bb0);
                    C[mt][ntin][3] = fmaf(pv[mt][1], w1v, bb1);
                }
            }
            #pragma unroll
            for (int ks = 0; ks < 2; ks++)
                #pragma unroll
                for (int mt = 0; mt < 2; mt++)
                    #pragma unroll
                    for (int ntin = 0; ntin < 2; ntin++)
                        mma16816(C[mt][ntin], Ah[mt][ks], Bf[ks][ntin]);
            // relu + fp16 pack -> transient Hh_p, then GEMM2 ks=p into C2
            #pragma unroll
            for (int mt = 0; mt < 2; mt++) {
                uint32_t Hp[4];
                #pragma unroll
                for (int q = 0; q < 4; q++) {
                    int ntin = q >> 1;
                    float hA = fmaxf(C[mt][ntin][(q & 1) * 2],     0.f);
                    float hB = fmaxf(C[mt][ntin][(q & 1) * 2 + 1], 0.f);
                    Hp[q] = packh2(hA, hB);
                }
                #pragma unroll
                for (int nt = 0; nt < 4; nt++)
                    mma16816(C2[mt][nt], Hp, B2f[nt]);
            }
        }

        // ---- epilogue: out = C2 (b2 + alpha*g already folded in) ----
        {
            float* outb = out + (size_t)t * 4096;
            #pragma unroll
            for (int mt = 0; mt < 2; mt++) {
                int r0 = m0 + mt*16 + (lane >> 2);
                int r1 = r0 + 8;
                #pragma unroll
                for (int nt = 0; nt < 4; nt++) {
                    int n = nt*8 + nb;
                    *(float2*)(outb + r0*32 + n) = make_float2(C2[mt][nt][0], C2[mt][nt][1]);
                    *(float2*)(outb + r1*32 + n) = make_float2(C2[mt][nt][2], C2[mt][nt][3]);
                }
            }
        }
        cur ^= 1;
    }
}

extern "C" void kernel_launch(void* const* d_in, const int* in_sizes, int n_in,
                              void* d_out, int out_size) {
    const float* grid = (const float*)d_in[0];
    const float* pot  = (const float*)d_in[1];
    const float* W1   = (const float*)d_in[2];
    const float* b1   = (const float*)d_in[3];
    const float* W2   = (const float*)d_in[4];
    const float* b2   = (const float*)d_in[5];
    float* out = (float*)d_out;

    cudaFuncSetAttribute(be_mma, cudaFuncAttributeMaxDynamicSharedMemorySize, SMEMSZ);
    be_mma<<<GRIDC, 128, SMEMSZ>>>(grid, pot, W1, b1, W2, b2, out);
}

// round 16
// speedup vs baseline: 2.2136x; 1.0573x over previous
#include <cuda_runtime.h>
#include <cstdint>

#define ALPHAF 0.3f
#define PATW   0.1f

#define GRIDC  912          // 152 SMs x 6 CTAs, persistent
#define NTILES 8192

// ---- dynamic smem layout (bytes) ----
// Single g buffer in FRAGMENT order: per warp 4096B = 16 slots x 256B.
// slot s = (mt*4 + j)*2 + h holds 8x8 fp32 block rows (m0+mt*16+h*8..+7),
// cols (j*8..j*8+7), entry (r&7, colpair p) at offset (r*4+p)*8 (lane-major).
#define O_G    0        // g frag buf: 4 warps x 4096 = 16384 (raw-W staging at init)
#define O_B1   16384    // B1 image: 64 rows x 40 halfs = 5120
#define O_B2   21504    // B2 image: 32 rows x 72 halfs = 4608
#define O_P    26112    // pot buf: 128 f32 = 512
#define O_B1S  26624    // b1: 64 f32
#define O_W1P  26880    // W1[32][:]: 64 f32
#define O_B2S  27136    // b2: 32 f32
#define SMEMSZ 27264

#define B1STR 40    // halfs (80B rows, conflict-free)
#define B2STR 72    // halfs (144B rows)

static __device__ __forceinline__ void ldm4(uint32_t* r, uint32_t addr) {
    asm volatile("ldmatrix.sync.aligned.m8n8.x4.shared.b16 {%0,%1,%2,%3}, [%4];"
                 : "=r"(r[0]), "=r"(r[1]), "=r"(r[2]), "=r"(r[3]) : "r"(addr));
}
static __device__ __forceinline__ void mma16816(float* c, const uint32_t* a, const uint32_t* b) {
    asm volatile(
        "mma.sync.aligned.m16n8k16.row.col.f32.f16.f16.f32 "
        "{%0,%1,%2,%3},{%4,%5,%6,%7},{%8,%9},{%0,%1,%2,%3};"
        : "+f"(c[0]), "+f"(c[1]), "+f"(c[2]), "+f"(c[3])
        : "r"(a[0]), "r"(a[1]), "r"(a[2]), "r"(a[3]), "r"(b[0]), "r"(b[1]));
}
static __device__ __forceinline__ uint32_t packh2(float lo, float hi) {
    uint32_t r;
    asm("{\n\t.reg .f16 l, h;\n\t"
        "cvt.rn.f16.f32 l, %1;\n\t"
        "cvt.rn.f16.f32 h, %2;\n\t"
        "mov.b32 %0, {l, h};\n\t}"
        : "=r"(r) : "f"(lo), "f"(hi));
    return r;
}
static __device__ __forceinline__ void cpa16(uint32_t dst, const void* src) {
    asm volatile("cp.async.ca.shared.global [%0], [%1], 16;" :: "r"(dst), "l"(src));
}

__global__ void __launch_bounds__(128, 6)
be_mma(const float* __restrict__ grid, const float* __restrict__ pot,
       const float* __restrict__ W1,   const float* __restrict__ b1,
       const float* __restrict__ W2,   const float* __restrict__ b2,
       float* __restrict__ out)
{
    extern __shared__ __align__(16) unsigned char sm[];
    float* b1s = (float*)(sm + O_B1S);
    float* w1p = (float*)(sm + O_W1P);
    float* b2s = (float*)(sm + O_B2S);
    unsigned short* img1 = (unsigned short*)(sm + O_B1);
    unsigned short* img2 = (unsigned short*)(sm + O_B2);

    const int tid  = threadIdx.x;
    const int lane = tid & 31;
    const int w    = tid >> 5;
    const int m0   = w * 32;

    const uint32_t gwb  = (uint32_t)__cvta_generic_to_shared(sm + O_G) + w * 4096;
    const uint32_t b1_b = (uint32_t)__cvta_generic_to_shared(sm + O_B1);
    const uint32_t b2_b = (uint32_t)__cvta_generic_to_shared(sm + O_B2);
    const uint32_t pbb  = (uint32_t)__cvta_generic_to_shared(sm + O_P);

    // per-lane constants for the fragment-order cp.async scatter
    const int cc_j  = (lane & 7) >> 1;
    const int cc_p0 = (lane & 1) * 2;
    const int cc_rb = lane >> 3;

    // ===== one-time weight build (two phases; raw staging inside g region) ==
    {
        float* rw = (float*)(sm + O_G);
        // phase A: W1 (2112 f32)
        #pragma unroll
        for (int i = tid; i < 2112; i += 128) rw[i] = W1[i];
        if (tid < 64) b1s[tid] = b1[tid];
        if (tid < 32) b2s[tid] = b2[tid];
        __syncthreads();
        if (tid < 64) {
            const int n = tid;
            uint32_t ph[16];
            #pragma unroll
            for (int kk = 0; kk < 16; kk++)
                ph[kk] = packh2(rw[(2*kk)*64 + n], rw[(2*kk+1)*64 + n]);
            uint4* dh = (uint4*)(img1 + n * B1STR);
            #pragma unroll
            for (int q = 0; q < 4; q++)
                dh[q] = make_uint4(ph[4*q], ph[4*q+1], ph[4*q+2], ph[4*q+3]);
            w1p[n] = rw[32 * 64 + n];
        }
        __syncthreads();
        // phase B: W2 (2048 f32)
        #pragma unroll
        for (int i = tid; i < 2048; i += 128) rw[i] = W2[i];
        __syncthreads();
        if (tid < 64) {
            const int n2 = tid >> 1;
            const int kh = (tid & 1) * 32;
            uint32_t ph[16];
            #pragma unroll
            for (int kk = 0; kk < 16; kk++) {
                int k = kh + 2 * kk;
                ph[kk] = packh2(rw[k*32 + n2], rw[(k+1)*32 + n2]);
            }
            uint4* dh = (uint4*)(img2 + n2 * B2STR + kh);
            #pragma unroll
            for (int q = 0; q < 4; q++)
                dh[q] = make_uint4(ph[4*q], ph[4*q+1], ph[4*q+2], ph[4*q+3]);
        }
        __syncthreads();
    }

    // ===== prologue: prefetch tile-0 warp slice into g buf (frag order) ====
    {
        const float* src = grid + (size_t)blockIdx.x * 4096 + m0 * 32;
        #pragma unroll
        for (int cc = 0; cc < 8; cc++) {
            int f   = lane + 32 * cc;
            int row = cc_rb + 4 * cc;
            int mt = row >> 4, h = (row >> 3) & 1, rr = row & 7;
            uint32_t dst = gwb + (uint32_t)(((mt*4 + cc_j)*2 + h)*256 + (rr*4 + cc_p0)*8);
            cpa16(dst, src + f * 4);
        }
        if (lane < 8)
            cpa16(pbb + (uint32_t)(m0 + lane * 4) * 4,
                  pot + (size_t)blockIdx.x * 128 + m0 + lane * 4);
        asm volatile("cp.async.commit_group;");
    }

    // ===== persistent per-warp tile loop ====================================
    const float* psm = (const float*)(sm + O_P);
    const int nb = (lane & 3) * 2;

    for (int t = blockIdx.x; t < NTILES; t += GRIDC) {
        asm volatile("cp.async.wait_group 0;");          // tile t resident

        // ---- load g fragments (conflict-free LDS.64) + pot (before prefetch!)
        float2 G[2][4][2];
        #pragma unroll
        for (int mt = 0; mt < 2; mt++)
            #pragma unroll
            for (int j = 0; j < 4; j++)
                #pragma unroll
                for (int h = 0; h < 2; h++) {
                    uint32_t a = gwb + (uint32_t)((((mt*4 + j)*2 + h)*256) + lane*8);
                    float2 v;
                    asm volatile("ld.shared.v2.f32 {%0,%1}, [%2];"
                                 : "=f"(v.x), "=f"(v.y) : "r"(a));
                    G[mt][j][h] = v;
                }
        float pv[2][2];
        #pragma unroll
        for (int mt = 0; mt < 2; mt++) {
            pv[mt][0] = psm[m0 + mt*16 + (lane >> 2)];
            pv[mt][1] = psm[m0 + mt*16 + (lane >> 2) + 8];
        }

        // ---- row norms via quad shfl ----
        float pg[2][2] = {{0.f,0.f},{0.f,0.f}}, pc[2][2] = {{0.f,0.f},{0.f,0.f}};
        #pragma unroll
        for (int mt = 0; mt < 2; mt++)
            #pragma unroll
            for (int h = 0; h < 2; h++)
                #pragma unroll
                for (int j = 0; j < 4; j++) {
                    float x = G[mt][j][h].x, y = G[mt][j][h].y;
                    float qx = x*x, qy = y*y;
                    pg[mt][h] += qx + qy;
                    float cx = qx*x, cy = qy*y;
                    pc[mt][h] = fmaf(cx, cx, pc[mt][h]);
                    pc[mt][h] = fmaf(cy, cy, pc[mt][h]);
                }
        float tt[2][2];
        #pragma unroll
        for (int mt = 0; mt < 2; mt++)
            #pragma unroll
            for (int h = 0; h < 2; h++) {
                float a = pg[mt][h], b = pc[mt][h];
                a += __shfl_xor_sync(0xffffffffu, a, 1);
                a += __shfl_xor_sync(0xffffffffu, a, 2);
                b += __shfl_xor_sync(0xffffffffu, b, 1);
                b += __shfl_xor_sync(0xffffffffu, b, 2);
                tt[mt][h] = PATW * sqrtf(a) * rsqrtf(b);
            }

        // ---- x = g + t*g^3 -> fp16 A fragments ----
        uint32_t Ah[2][2][4];
        #pragma unroll
        for (int mt = 0; mt < 2; mt++)
            #pragma unroll
            for (int ks = 0; ks < 2; ks++)
                #pragma unroll
                for (int half = 0; half < 2; half++)
                    #pragma unroll
                    for (int h = 0; h < 2; h++) {
                        float2 gv = G[mt][2*ks + half][h];
                        float T = tt[mt][h];
                        float x0 = fmaf(T * gv.x * gv.x, gv.x, gv.x);
                        float x1 = fmaf(T * gv.y * gv.y, gv.y, gv.y);
                        Ah[mt][ks][half*2 + h] = packh2(x0, x1);
                    }

        // ---- C2 pre-init: b2 + alpha*g (last G use; G dies here) ----
        float C2[2][4][4];
        #pragma unroll
        for (int mt = 0; mt < 2; mt++)
            #pragma unroll
            for (int nt = 0; nt < 4; nt++) {
                int n = nt*8 + nb;
                float bb0 = b2s[n], bb1 = b2s[n+1];
                C2[mt][nt][0] = fmaf(ALPHAF, G[mt][nt][0].x, bb0);
                C2[mt][nt][1] = fmaf(ALPHAF, G[mt][nt][0].y, bb1);
                C2[mt][nt][2] = fmaf(ALPHAF, G[mt][nt][1].x, bb0);
                C2[mt][nt][3] = fmaf(ALPHAF, G[mt][nt][1].y, bb1);
            }

        // ---- prefetch tile t+GRIDC into the SAME buffer (g dead now) ----
        {
            int tn = t + GRIDC;
            if (tn < NTILES) {
                const float* src = grid + (size_t)tn * 4096 + m0 * 32;
                #pragma unroll
                for (int cc = 0; cc < 8; cc++) {
                    int f   = lane + 32 * cc;
                    int row = cc_rb + 4 * cc;
                    int mt = row >> 4, h = (row >> 3) & 1, rr = row & 7;
                    uint32_t dst = gwb + (uint32_t)(((mt*4 + cc_j)*2 + h)*256 + (rr*4 + cc_p0)*8);
                    cpa16(dst, src + f * 4);
                }
                if (lane < 8)
                    cpa16(pbb + (uint32_t)(m0 + lane * 4) * 4,
                          pot + (size_t)tn * 128 + m0 + lane * 4);
            }
            asm volatile("cp.async.commit_group;");
        }

        // ---- fused GEMM1+GEMM2 over nt-pair blocks p (mt-split for regs) ----
        #pragma unroll
        for (int p = 0; p < 4; p++) {
            uint32_t B2f[4][2];
            #pragma unroll
            for (int np = 0; np < 2; np++) {
                uint32_t a = b2_b + (uint32_t)(np*16 + ((lane>>4)<<3) + (lane&7)) * (B2STR*2)
                           + (uint32_t)(p*16)*2 + (((lane>>3)&1) << 4);
                ldm4(&B2f[2*np][0], a);
            }
            uint32_t Bf[2][2][2];
            #pragma unroll
            for (int ks = 0; ks < 2; ks++) {
                uint32_t a = b1_b + (uint32_t)(p*16 + ((lane>>4)<<3) + (lane&7)) * (B1STR*2)
                           + (uint32_t)(ks*16)*2 + (((lane>>3)&1) << 4);
                ldm4(&Bf[ks][0][0], a);
            }
            #pragma unroll
            for (int mt = 0; mt < 2; mt++) {
                float C[2][4];
                #pragma unroll
                for (int ntin = 0; ntin < 2; ntin++) {
                    int n = (2*p + ntin)*8 + nb;
                    float bb0 = b1s[n], bb1 = b1s[n+1], w0 = w1p[n], w1v = w1p[n+1];
                    C[ntin][0] = fmaf(pv[mt][0], w0,  bb0);
                    C[ntin][1] = fmaf(pv[mt][0], w1v, bb1);
                    C[ntin][2] = fmaf(pv[mt][1], w0,  bb0);
                    C[ntin][3] = fmaf(pv[mt][1], w1v, bb1);
                }
                #pragma unroll
                for (int ks = 0; ks < 2; ks++)
                    #pragma unroll
                    for (int ntin = 0; ntin < 2; ntin++)
                        mma16816(C[ntin], Ah[mt][ks], Bf[ks][ntin]);
                uint32_t Hp[4];
                #pragma unroll
                for (int q = 0; q < 4; q++) {
                    int ntin = q >> 1;
                    float hA = fmaxf(C[ntin][(q & 1) * 2],     0.f);
                    float hB = fmaxf(C[ntin][(q & 1) * 2 + 1], 0.f);
                    Hp[q] = packh2(hA, hB);
                }
                #pragma unroll
                for (int nt = 0; nt < 4; nt++)
                    mma16816(C2[mt][nt], Hp, B2f[nt]);
            }
        }

        // ---- epilogue: out = C2 (b2 + alpha*g already folded in) ----
        {
            float* outb = out + (size_t)t * 4096;
            #pragma unroll
            for (int mt = 0; mt < 2; mt++) {
                int r0 = m0 + mt*16 + (lane >> 2);
                int r1 = r0 + 8;
                #pragma unroll
                for (int nt = 0; nt < 4; nt++) {
                    int n = nt*8 + nb;
                    *(float2*)(outb + r0*32 + n) = make_float2(C2[mt][nt][0], C2[mt][nt][1]);
                    *(float2*)(outb + r1*32 + n) = make_float2(C2[mt][nt][2], C2[mt][nt][3]);
                }
            }
        }
    }
}

extern "C" void kernel_launch(void* const* d_in, const int* in_sizes, int n_in,
                              void* d_out, int out_size) {
    const float* grid = (const float*)d_in[0];
    const float* pot  = (const float*)d_in[1];
    const float* W1   = (const float*)d_in[2];
    const float* b1   = (const float*)d_in[3];
    const float* W2   = (const float*)d_in[4];
    const float* b2   = (const float*)d_in[5];
    float* out = (float*)d_out;

    cudaFuncSetAttribute(be_mma, cudaFuncAttributeMaxDynamicSharedMemorySize, SMEMSZ);
    be_mma<<<GRIDC, 128, SMEMSZ>>>(grid, pot, W1, b1, W2, b2, out);
}